// round 5
// baseline (speedup 1.0000x reference)
#include <cuda_runtime.h>
#include <math.h>

#define BB 256
#define TT 2048

// ---------------- scratch (static device memory; no allocations) ----------------
__device__ float g_y1 [(size_t)BB * TT * 256];   // layer1 output (B,T,256)
__device__ float g_xg2[(size_t)BB * TT * 512];   // layer2 input gates
__device__ float g_y2 [(size_t)BB * TT * 128];   // layer2 output (B,T,128)
__device__ float g_xg3[(size_t)BB * TT * 128];   // layer3 input gates
__device__ float g_sum3[BB * 32];                // time-mean of layer3 output

__device__ __forceinline__ float sigf(float v) { return 1.0f / (1.0f + __expf(-v)); }

// =========================================================================
// Layer 1: fused x-projection (D=2) + recurrence. H=128, 4H=512.
// grid (64, 2): x = batch tile (4 batches), y = direction. 512 threads,
// thread r owns gate row r for all 4 batches. Whh row: 64 regs + 64 smem.
// =========================================================================
#define L1_KREG 64
#define L1_KS   64
#define L1_SMEM_BYTES ((L1_KS * 512 + 4 * 128 + 4 * 512) * 4)

__global__ __launch_bounds__(512, 1) void lstm1_kernel(
    const float* __restrict__ x,     // (256,2048,2)
    const float* __restrict__ Wih,   // (2,512,2)
    const float* __restrict__ Whh,   // (2,512,128)
    const float* __restrict__ bih,   // (2,512)
    const float* __restrict__ bhh,   // (2,512)
    float* __restrict__ y1)          // (256,2048,256)
{
    extern __shared__ float sm[];
    float* sWk = sm;                    // [64][512] k-major
    float* sh  = sm + L1_KS * 512;      // [4][128]
    float* sg  = sh + 4 * 128;          // [4][512]

    const int dir = blockIdx.y;
    const int bg0 = blockIdx.x * 4;
    const int r   = threadIdx.x;
    const float* WhhD = Whh + (size_t)dir * 512 * 128;

    for (int i = r; i < L1_KS * 512; i += 512) {
        int kk = i >> 9, rr = i & 511;
        sWk[i] = WhhD[rr * 128 + L1_KREG + kk];
    }
    float Wreg[L1_KREG];
    #pragma unroll
    for (int k = 0; k < L1_KREG; k++) Wreg[k] = WhhD[r * 128 + k];

    const float wx0  = Wih[dir * 1024 + r * 2 + 0];
    const float wx1  = Wih[dir * 1024 + r * 2 + 1];
    const float bias = bih[dir * 512 + r] + bhh[dir * 512 + r];
    const int   gate = r >> 7;          // 0=i 1=f 2=g 3=o

    for (int i = r; i < 4 * 128; i += 512) sh[i] = 0.0f;
    // combine-role state: thread tid handles (batch cb, unit j)
    const int cb = r >> 7;
    const int j  = r & 127;
    float cc = 0.0f;
    __syncthreads();

    for (int s = 0; s < TT; s++) {
        const int t = dir ? (TT - 1 - s) : s;
        float2 xv0 = __ldg((const float2*)(x + ((size_t)(bg0 + 0) * TT + t) * 2));
        float2 xv1 = __ldg((const float2*)(x + ((size_t)(bg0 + 1) * TT + t) * 2));
        float2 xv2 = __ldg((const float2*)(x + ((size_t)(bg0 + 2) * TT + t) * 2));
        float2 xv3 = __ldg((const float2*)(x + ((size_t)(bg0 + 3) * TT + t) * 2));

        float a0 = 0.f, a1 = 0.f, a2 = 0.f, a3 = 0.f;
        #pragma unroll
        for (int k = 0; k < L1_KREG; k += 4) {
            float4 h0 = *(const float4*)(sh +   0 + k);
            float4 h1 = *(const float4*)(sh + 128 + k);
            float4 h2 = *(const float4*)(sh + 256 + k);
            float4 h3 = *(const float4*)(sh + 384 + k);
            a0 = fmaf(Wreg[k], h0.x, a0); a0 = fmaf(Wreg[k+1], h0.y, a0);
            a0 = fmaf(Wreg[k+2], h0.z, a0); a0 = fmaf(Wreg[k+3], h0.w, a0);
            a1 = fmaf(Wreg[k], h1.x, a1); a1 = fmaf(Wreg[k+1], h1.y, a1);
            a1 = fmaf(Wreg[k+2], h1.z, a1); a1 = fmaf(Wreg[k+3], h1.w, a1);
            a2 = fmaf(Wreg[k], h2.x, a2); a2 = fmaf(Wreg[k+1], h2.y, a2);
            a2 = fmaf(Wreg[k+2], h2.z, a2); a2 = fmaf(Wreg[k+3], h2.w, a2);
            a3 = fmaf(Wreg[k], h3.x, a3); a3 = fmaf(Wreg[k+1], h3.y, a3);
            a3 = fmaf(Wreg[k+2], h3.z, a3); a3 = fmaf(Wreg[k+3], h3.w, a3);
        }
        #pragma unroll
        for (int kk = 0; kk < L1_KS; kk += 4) {
            const int k = L1_KREG + kk;
            float w0 = sWk[(kk + 0) * 512 + r];
            float w1 = sWk[(kk + 1) * 512 + r];
            float w2 = sWk[(kk + 2) * 512 + r];
            float w3 = sWk[(kk + 3) * 512 + r];
            float4 h0 = *(const float4*)(sh +   0 + k);
            float4 h1 = *(const float4*)(sh + 128 + k);
            float4 h2 = *(const float4*)(sh + 256 + k);
            float4 h3 = *(const float4*)(sh + 384 + k);
            a0 = fmaf(w0, h0.x, a0); a0 = fmaf(w1, h0.y, a0);
            a0 = fmaf(w2, h0.z, a0); a0 = fmaf(w3, h0.w, a0);
            a1 = fmaf(w0, h1.x, a1); a1 = fmaf(w1, h1.y, a1);
            a1 = fmaf(w2, h1.z, a1); a1 = fmaf(w3, h1.w, a1);
            a2 = fmaf(w0, h2.x, a2); a2 = fmaf(w1, h2.y, a2);
            a2 = fmaf(w2, h2.z, a2); a2 = fmaf(w3, h2.w, a2);
            a3 = fmaf(w0, h3.x, a3); a3 = fmaf(w1, h3.y, a3);
            a3 = fmaf(w2, h3.z, a3); a3 = fmaf(w3, h3.w, a3);
        }

        float v0 = fmaf(wx0, xv0.x, fmaf(wx1, xv0.y, bias + a0));
        float v1 = fmaf(wx0, xv1.x, fmaf(wx1, xv1.y, bias + a1));
        float v2 = fmaf(wx0, xv2.x, fmaf(wx1, xv2.y, bias + a2));
        float v3 = fmaf(wx0, xv3.x, fmaf(wx1, xv3.y, bias + a3));
        if (gate == 2) {
            sg[0*512 + r] = tanhf(v0); sg[1*512 + r] = tanhf(v1);
            sg[2*512 + r] = tanhf(v2); sg[3*512 + r] = tanhf(v3);
        } else {
            sg[0*512 + r] = sigf(v0); sg[1*512 + r] = sigf(v1);
            sg[2*512 + r] = sigf(v2); sg[3*512 + r] = sigf(v3);
        }
        __syncthreads();

        // combine: thread handles (batch cb, unit j)
        {
            float i_ = sg[cb*512 + j];
            float f_ = sg[cb*512 + j + 128];
            float gg = sg[cb*512 + j + 256];
            float o_ = sg[cb*512 + j + 384];
            cc = fmaf(f_, cc, i_ * gg);
            float h = o_ * tanhf(cc);
            sh[cb*128 + j] = h;
            y1[((size_t)(bg0 + cb) * TT + t) * 256 + dir * 128 + j] = h;
        }
        __syncthreads();
    }
}

// =========================================================================
// Tiled fp32 GEMM + bias: C[m][n] = sum_k A[m][k]*B[n][k] + b1[n] + b2[n]
// BM=128, BN=64, BK=16, 256 threads, 8x4 microtile.
// grid (N/64, M/128). K, M, N multiples of 16/128/64.
// =========================================================================
__global__ __launch_bounds__(256) void gemm_bias_kernel(
    const float* __restrict__ A, const float* __restrict__ B,
    const float* __restrict__ b1, const float* __restrict__ b2,
    float* __restrict__ C, int N, int K)
{
    __shared__ float As[16][128];
    __shared__ float Bs[16][64];
    const int m0 = blockIdx.y * 128;
    const int n0 = blockIdx.x * 64;
    const int tid = threadIdx.x;
    const int tx = tid & 15, ty = tid >> 4;
    const int lrow = tid >> 2;
    const int lcol = (tid & 3) << 2;

    float acc[8][4];
    #pragma unroll
    for (int i = 0; i < 8; i++)
        #pragma unroll
        for (int jj = 0; jj < 4; jj++) acc[i][jj] = 0.0f;

    for (int k0 = 0; k0 < K; k0 += 16) {
        #pragma unroll
        for (int rr = 0; rr < 2; rr++) {
            int row = lrow + rr * 64;
            float4 v = *(const float4*)&A[(size_t)(m0 + row) * K + k0 + lcol];
            As[lcol+0][row] = v.x; As[lcol+1][row] = v.y;
            As[lcol+2][row] = v.z; As[lcol+3][row] = v.w;
        }
        {
            float4 v = *(const float4*)&B[(size_t)(n0 + lrow) * K + k0 + lcol];
            Bs[lcol+0][lrow] = v.x; Bs[lcol+1][lrow] = v.y;
            Bs[lcol+2][lrow] = v.z; Bs[lcol+3][lrow] = v.w;
        }
        __syncthreads();
        #pragma unroll
        for (int k = 0; k < 16; k++) {
            float4 a0 = *(const float4*)&As[k][ty * 8];
            float4 a1 = *(const float4*)&As[k][ty * 8 + 4];
            float4 bv = *(const float4*)&Bs[k][tx * 4];
            float ar[8] = {a0.x, a0.y, a0.z, a0.w, a1.x, a1.y, a1.z, a1.w};
            float br[4] = {bv.x, bv.y, bv.z, bv.w};
            #pragma unroll
            for (int i = 0; i < 8; i++)
                #pragma unroll
                for (int jj = 0; jj < 4; jj++)
                    acc[i][jj] = fmaf(ar[i], br[jj], acc[i][jj]);
        }
        __syncthreads();
    }
    #pragma unroll
    for (int i = 0; i < 8; i++) {
        size_t row = (size_t)(m0 + ty * 8 + i);
        #pragma unroll
        for (int jj = 0; jj < 4; jj++) {
            int col = n0 + tx * 4 + jj;
            C[row * N + col] = acc[i][jj] + b1[col] + b2[col];
        }
    }
}

// =========================================================================
// Layer 2 recurrence: H=64, 4H=256. 512 threads = 2 (batch,dir) pairs.
// Weights fully in registers (64/thread). grid 256 CTAs.
// =========================================================================
__global__ __launch_bounds__(512, 1) void lstm2_kernel(
    const float* __restrict__ xg,    // (B*T, 512)
    const float* __restrict__ Whh,   // (2,256,64)
    float* __restrict__ y2)          // (B,T,128)
{
    __shared__ float sh[2 * 64];
    __shared__ float sg[2 * 256];
    const int tid = threadIdx.x;
    const int pl = tid >> 8;       // pair 0/1
    const int r  = tid & 255;      // gate row
    const int pg = blockIdx.x * 2 + pl;
    const int b  = pg >> 1;
    const int dir = pg & 1;
    const int gate = r >> 6;
    const int j = r & 63;

    float w[64];
    #pragma unroll
    for (int k = 0; k < 64; k++) w[k] = Whh[(size_t)dir * 256 * 64 + r * 64 + k];

    if (tid < 128) sh[tid] = 0.0f;
    float cc = 0.0f;
    __syncthreads();

    const float* xgb = xg + (size_t)b * TT * 512 + dir * 256 + r;
    for (int s = 0; s < TT; s++) {
        const int t = dir ? (TT - 1 - s) : s;
        float xt = __ldg(xgb + (size_t)t * 512);

        float a = 0.0f;
        #pragma unroll
        for (int k = 0; k < 64; k += 4) {
            float4 hv = *(const float4*)(sh + pl * 64 + k);
            a = fmaf(w[k], hv.x, a); a = fmaf(w[k+1], hv.y, a);
            a = fmaf(w[k+2], hv.z, a); a = fmaf(w[k+3], hv.w, a);
        }
        float v = xt + a;
        sg[pl * 256 + r] = (gate == 2) ? tanhf(v) : sigf(v);
        __syncthreads();

        if (r < 64) {
            float i_ = sg[pl*256 + j];
            float f_ = sg[pl*256 + j + 64];
            float gg = sg[pl*256 + j + 128];
            float o_ = sg[pl*256 + j + 192];
            cc = fmaf(f_, cc, i_ * gg);
            float h = o_ * tanhf(cc);
            sh[pl * 64 + j] = h;
            y2[((size_t)b * TT + t) * 128 + dir * 64 + j] = h;
        }
        __syncthreads();
    }
}

// =========================================================================
// Layer 3 recurrence + time mean: H=16, 4H=64. 512 threads = 8 pairs.
// grid 64 CTAs, single wave.
// =========================================================================
__global__ __launch_bounds__(512, 1) void lstm3_kernel(
    const float* __restrict__ xg,    // (B*T, 128)
    const float* __restrict__ Whh,   // (2,64,16)
    float* __restrict__ s3)          // (B,32) mean
{
    __shared__ float sh[8 * 16];
    __shared__ float sg[8 * 64];
    const int tid = threadIdx.x;
    const int pl = tid >> 6;       // pair 0..7
    const int r  = tid & 63;
    const int pg = blockIdx.x * 8 + pl;
    const int b  = pg >> 1;
    const int dir = pg & 1;
    const int gate = r >> 4;
    const int j = r & 15;

    float w[16];
    #pragma unroll
    for (int k = 0; k < 16; k++) w[k] = Whh[(size_t)dir * 64 * 16 + r * 16 + k];

    if (tid < 128) sh[tid] = 0.0f;
    float cc = 0.0f, sum = 0.0f;
    __syncthreads();

    const float* xgb = xg + (size_t)b * TT * 128 + dir * 64 + r;
    for (int s = 0; s < TT; s++) {
        const int t = dir ? (TT - 1 - s) : s;
        float xt = __ldg(xgb + (size_t)t * 128);

        float a = 0.0f;
        #pragma unroll
        for (int k = 0; k < 16; k += 4) {
            float4 hv = *(const float4*)(sh + pl * 16 + k);
            a = fmaf(w[k], hv.x, a); a = fmaf(w[k+1], hv.y, a);
            a = fmaf(w[k+2], hv.z, a); a = fmaf(w[k+3], hv.w, a);
        }
        float v = xt + a;
        sg[pl * 64 + r] = (gate == 2) ? tanhf(v) : sigf(v);
        __syncthreads();

        if (r < 16) {
            float i_ = sg[pl*64 + j];
            float f_ = sg[pl*64 + j + 16];
            float gg = sg[pl*64 + j + 32];
            float o_ = sg[pl*64 + j + 48];
            cc = fmaf(f_, cc, i_ * gg);
            float h = o_ * tanhf(cc);
            sh[pl * 16 + j] = h;
            sum += h;
        }
        __syncthreads();
    }
    if (r < 16) s3[b * 32 + dir * 16 + j] = sum * (1.0f / TT);
}

// =========================================================================
// MLP head: (256,32) -> 64 relu -> 16 relu -> 20. One thread per batch.
// =========================================================================
__global__ void mlp_kernel(
    const float* __restrict__ s3,
    const float* __restrict__ hW1, const float* __restrict__ hb1,
    const float* __restrict__ hW2, const float* __restrict__ hb2,
    const float* __restrict__ hW3, const float* __restrict__ hb3,
    float* __restrict__ out)
{
    int b = blockIdx.x * blockDim.x + threadIdx.x;
    if (b >= BB) return;
    float s[32];
    #pragma unroll
    for (int k = 0; k < 32; k++) s[k] = s3[b * 32 + k];
    float h1[64];
    for (int o = 0; o < 64; o++) {
        float a = hb1[o];
        #pragma unroll
        for (int k = 0; k < 32; k++) a = fmaf(s[k], hW1[o * 32 + k], a);
        h1[o] = fmaxf(a, 0.0f);
    }
    float h2[16];
    for (int o = 0; o < 16; o++) {
        float a = hb2[o];
        #pragma unroll
        for (int k = 0; k < 64; k++) a = fmaf(h1[k], hW2[o * 64 + k], a);
        h2[o] = fmaxf(a, 0.0f);
    }
    for (int o = 0; o < 20; o++) {
        float a = hb3[o];
        #pragma unroll
        for (int k = 0; k < 16; k++) a = fmaf(h2[k], hW3[o * 16 + k], a);
        out[b * 20 + o] = a;
    }
}

// =========================================================================
extern "C" void kernel_launch(void* const* d_in, const int* in_sizes, int n_in,
                              void* d_out, int out_size)
{
    const float* x    = (const float*)d_in[0];
    const float* Wih1 = (const float*)d_in[1];
    const float* Whh1 = (const float*)d_in[2];
    const float* bih1 = (const float*)d_in[3];
    const float* bhh1 = (const float*)d_in[4];
    const float* Wih2 = (const float*)d_in[5];
    const float* Whh2 = (const float*)d_in[6];
    const float* bih2 = (const float*)d_in[7];
    const float* bhh2 = (const float*)d_in[8];
    const float* Wih3 = (const float*)d_in[9];
    const float* Whh3 = (const float*)d_in[10];
    const float* bih3 = (const float*)d_in[11];
    const float* bhh3 = (const float*)d_in[12];
    const float* hW1  = (const float*)d_in[13];
    const float* hb1  = (const float*)d_in[14];
    const float* hW2  = (const float*)d_in[15];
    const float* hb2  = (const float*)d_in[16];
    const float* hW3  = (const float*)d_in[17];
    const float* hb3  = (const float*)d_in[18];
    float* out = (float*)d_out;

    float *y1, *xg2, *y2, *xg3, *s3;
    cudaGetSymbolAddress((void**)&y1,  g_y1);
    cudaGetSymbolAddress((void**)&xg2, g_xg2);
    cudaGetSymbolAddress((void**)&y2,  g_y2);
    cudaGetSymbolAddress((void**)&xg3, g_xg3);
    cudaGetSymbolAddress((void**)&s3,  g_sum3);

    static bool attr_set = false;
    if (!attr_set) {
        cudaFuncSetAttribute(lstm1_kernel,
            cudaFuncAttributeMaxDynamicSharedMemorySize, L1_SMEM_BYTES);
        attr_set = true;
    }

    const int M = BB * TT;

    lstm1_kernel<<<dim3(64, 2), 512, L1_SMEM_BYTES>>>(x, Wih1, Whh1, bih1, bhh1, y1);
    gemm_bias_kernel<<<dim3(512 / 64, M / 128), 256>>>(y1, Wih2, bih2, bhh2, xg2, 512, 256);
    lstm2_kernel<<<256, 512>>>(xg2, Whh2, y2);
    gemm_bias_kernel<<<dim3(128 / 64, M / 128), 256>>>(y2, Wih3, bih3, bhh3, xg3, 128, 128);
    lstm3_kernel<<<64, 512>>>(xg3, Whh3, s3);
    mlp_kernel<<<1, 256>>>(s3, hW1, hb1, hW2, hb2, hW3, hb3, out);
}

// round 6
// speedup vs baseline: 1.0826x; 1.0826x over previous
#include <cuda_runtime.h>
#include <math.h>

#define BB 256
#define TT 2048

// ---------------- scratch (static device memory; no allocations) ----------------
__device__ float g_y1 [(size_t)BB * TT * 256];   // layer1 output (B,T,256)
__device__ float g_xg2[(size_t)BB * TT * 512];   // layer2 input gates
__device__ float g_y2 [(size_t)BB * TT * 128];   // layer2 output (B,T,128)
__device__ float g_xg3[(size_t)BB * TT * 128];   // layer3 input gates
__device__ float g_sum3[BB * 32];                // time-mean of layer3 output

typedef unsigned long long ull;

// ---- fast helpers -------------------------------------------------------
__device__ __forceinline__ float mysig(float v) {
    return __fdividef(1.0f, 1.0f + __expf(-v));
}
__device__ __forceinline__ float mytanh(float v) {
    // 1 - 2/(1+e^{2v}); saturates correctly for |v| large, no NaN path
    float e = __expf(2.0f * v);
    return 1.0f - 2.0f * __fdividef(1.0f, 1.0f + e);
}
__device__ __forceinline__ ull pk(float lo, float hi) {
    ull r; asm("mov.b64 %0, {%1, %2};" : "=l"(r) : "f"(lo), "f"(hi)); return r;
}
__device__ __forceinline__ void upk(ull v, float& lo, float& hi) {
    asm("mov.b64 {%0, %1}, %2;" : "=f"(lo), "=f"(hi) : "l"(v));
}
__device__ __forceinline__ void fma2(ull& d, ull a, ull b) {
    asm("fma.rn.f32x2 %0, %1, %2, %0;" : "+l"(d) : "l"(a), "l"(b));
}

// =========================================================================
// Layer 1: fused x-projection (D=2) + recurrence. H=128, 4H=512.
// grid (64, 2). 512 threads: thread r owns gate row r for 4 batches.
// Whh row: 64 k in regs + 64 k in k-major smem. h stored [k][4b] so one
// LDS.128 yields both packed f32x2 batch-pairs.
// =========================================================================
#define L1_KREG 64
#define L1_KS   64
#define L1_SMEM_BYTES ((L1_KS * 512 + 128 * 4 + 4 * 512) * 4)

__global__ __launch_bounds__(512, 1) void lstm1_kernel(
    const float* __restrict__ x,     // (256,2048,2)
    const float* __restrict__ Wih,   // (2,512,2)
    const float* __restrict__ Whh,   // (2,512,128)
    const float* __restrict__ bih,   // (2,512)
    const float* __restrict__ bhh,   // (2,512)
    float* __restrict__ y1)          // (256,2048,256)
{
    extern __shared__ float sm[];
    float* sWk = sm;                    // [64][512] k-major, k in [64,128)
    float* sh4 = sm + L1_KS * 512;      // [128 k][4 b]
    float* sg  = sh4 + 128 * 4;         // [4 b][512 r]

    const int dir = blockIdx.y;
    const int bg0 = blockIdx.x * 4;
    const int r   = threadIdx.x;
    const float* WhhD = Whh + (size_t)dir * 512 * 128;

    for (int i = r; i < L1_KS * 512; i += 512) {
        int kk = i >> 9, rr = i & 511;
        sWk[i] = WhhD[rr * 128 + L1_KREG + kk];
    }
    float Wreg[L1_KREG];
    #pragma unroll
    for (int k = 0; k < L1_KREG; k++) Wreg[k] = WhhD[r * 128 + k];

    const float wx0  = Wih[dir * 1024 + r * 2 + 0];
    const float wx1  = Wih[dir * 1024 + r * 2 + 1];
    const float bias = bih[dir * 512 + r] + bhh[dir * 512 + r];
    const int   gate = r >> 7;          // 0=i 1=f 2=g 3=o
    const int   cb = r >> 7;            // combine: batch
    const int   j  = r & 127;           // combine: unit

    sh4[r] = 0.0f;                      // 512 entries, all threads
    float cc = 0.0f;
    __syncthreads();

    for (int s = 0; s < TT; s++) {
        const int t = dir ? (TT - 1 - s) : s;
        float2 xv0 = __ldg((const float2*)(x + ((size_t)(bg0 + 0) * TT + t) * 2));
        float2 xv1 = __ldg((const float2*)(x + ((size_t)(bg0 + 1) * TT + t) * 2));
        float2 xv2 = __ldg((const float2*)(x + ((size_t)(bg0 + 2) * TT + t) * 2));
        float2 xv3 = __ldg((const float2*)(x + ((size_t)(bg0 + 3) * TT + t) * 2));

        ull acc01 = 0ull, acc23 = 0ull;   // {0.f,0.f}
        #pragma unroll
        for (int k = 0; k < L1_KREG; k++) {
            ulonglong2 hb = *(const ulonglong2*)(sh4 + k * 4);  // broadcast
            ull wd = pk(Wreg[k], Wreg[k]);
            fma2(acc01, wd, hb.x);
            fma2(acc23, wd, hb.y);
        }
        #pragma unroll
        for (int kk = 0; kk < L1_KS; kk++) {
            const int k = L1_KREG + kk;
            float w = sWk[kk * 512 + r];
            ulonglong2 hb = *(const ulonglong2*)(sh4 + k * 4);
            ull wd = pk(w, w);
            fma2(acc01, wd, hb.x);
            fma2(acc23, wd, hb.y);
        }

        float a0, a1, a2, a3;
        upk(acc01, a0, a1); upk(acc23, a2, a3);
        float v0 = fmaf(wx0, xv0.x, fmaf(wx1, xv0.y, bias + a0));
        float v1 = fmaf(wx0, xv1.x, fmaf(wx1, xv1.y, bias + a1));
        float v2 = fmaf(wx0, xv2.x, fmaf(wx1, xv2.y, bias + a2));
        float v3 = fmaf(wx0, xv3.x, fmaf(wx1, xv3.y, bias + a3));
        if (gate == 2) {
            sg[0*512 + r] = mytanh(v0); sg[1*512 + r] = mytanh(v1);
            sg[2*512 + r] = mytanh(v2); sg[3*512 + r] = mytanh(v3);
        } else {
            sg[0*512 + r] = mysig(v0); sg[1*512 + r] = mysig(v1);
            sg[2*512 + r] = mysig(v2); sg[3*512 + r] = mysig(v3);
        }
        __syncthreads();

        // combine: thread handles (batch cb, unit j)
        {
            float i_ = sg[cb*512 + j];
            float f_ = sg[cb*512 + j + 128];
            float gg = sg[cb*512 + j + 256];
            float o_ = sg[cb*512 + j + 384];
            cc = fmaf(f_, cc, i_ * gg);
            float h = o_ * mytanh(cc);
            sh4[j * 4 + cb] = h;
            y1[((size_t)(bg0 + cb) * TT + t) * 256 + dir * 128 + j] = h;
        }
        __syncthreads();
    }
}

// =========================================================================
// Tiled fp32 GEMM + bias: C[m][n] = sum_k A[m][k]*B[n][k] + b1[n] + b2[n]
// BM=128, BN=64, BK=16, 256 threads, 8x4 microtile.
// =========================================================================
__global__ __launch_bounds__(256) void gemm_bias_kernel(
    const float* __restrict__ A, const float* __restrict__ B,
    const float* __restrict__ b1, const float* __restrict__ b2,
    float* __restrict__ C, int N, int K)
{
    __shared__ float As[16][128];
    __shared__ float Bs[16][64];
    const int m0 = blockIdx.y * 128;
    const int n0 = blockIdx.x * 64;
    const int tid = threadIdx.x;
    const int tx = tid & 15, ty = tid >> 4;
    const int lrow = tid >> 2;
    const int lcol = (tid & 3) << 2;

    float acc[8][4];
    #pragma unroll
    for (int i = 0; i < 8; i++)
        #pragma unroll
        for (int jj = 0; jj < 4; jj++) acc[i][jj] = 0.0f;

    for (int k0 = 0; k0 < K; k0 += 16) {
        #pragma unroll
        for (int rr = 0; rr < 2; rr++) {
            int row = lrow + rr * 64;
            float4 v = *(const float4*)&A[(size_t)(m0 + row) * K + k0 + lcol];
            As[lcol+0][row] = v.x; As[lcol+1][row] = v.y;
            As[lcol+2][row] = v.z; As[lcol+3][row] = v.w;
        }
        {
            float4 v = *(const float4*)&B[(size_t)(n0 + lrow) * K + k0 + lcol];
            Bs[lcol+0][lrow] = v.x; Bs[lcol+1][lrow] = v.y;
            Bs[lcol+2][lrow] = v.z; Bs[lcol+3][lrow] = v.w;
        }
        __syncthreads();
        #pragma unroll
        for (int k = 0; k < 16; k++) {
            float4 av0 = *(const float4*)&As[k][ty * 8];
            float4 av1 = *(const float4*)&As[k][ty * 8 + 4];
            float4 bv = *(const float4*)&Bs[k][tx * 4];
            float ar[8] = {av0.x, av0.y, av0.z, av0.w, av1.x, av1.y, av1.z, av1.w};
            float br[4] = {bv.x, bv.y, bv.z, bv.w};
            #pragma unroll
            for (int i = 0; i < 8; i++)
                #pragma unroll
                for (int jj = 0; jj < 4; jj++)
                    acc[i][jj] = fmaf(ar[i], br[jj], acc[i][jj]);
        }
        __syncthreads();
    }
    #pragma unroll
    for (int i = 0; i < 8; i++) {
        size_t row = (size_t)(m0 + ty * 8 + i);
        #pragma unroll
        for (int jj = 0; jj < 4; jj++) {
            int col = n0 + tx * 4 + jj;
            C[row * N + col] = acc[i][jj] + b1[col] + b2[col];
        }
    }
}

// =========================================================================
// Layer 2 recurrence: H=64, 4H=256. 256 threads, CTA = one (b,dir) chain.
// Weights in 64 KB dynamic smem, pre-packed as f32x2 k-pairs: sW2[kp][r].
// xt prefetched one step ahead. grid 512, ~3 CTAs/SM.
// =========================================================================
#define L2_SMEM_BYTES (32 * 256 * 8 + 64 * 4 + 256 * 4)

__global__ __launch_bounds__(256, 1) void lstm2_kernel(
    const float* __restrict__ xg,    // (B*T, 512)
    const float* __restrict__ Whh,   // (2,256,64)
    float* __restrict__ y2)          // (B,T,128)
{
    extern __shared__ char smraw[];
    ull*   sW2 = (ull*)smraw;                     // [32 kp][256 r]
    float* sh  = (float*)(smraw + 32 * 256 * 8);  // [64]
    float* sg  = sh + 64;                         // [256]

    const int r = threadIdx.x;
    const int b   = blockIdx.x >> 1;
    const int dir = blockIdx.x & 1;
    const int gate = r >> 6;
    const int j = r & 63;
    const float* WhhD = Whh + (size_t)dir * 256 * 64;

    for (int i = r; i < 32 * 256; i += 256) {
        int kp = i >> 8, rr = i & 255;
        sW2[i] = *(const ull*)(WhhD + rr * 64 + 2 * kp);
    }
    if (r < 64) sh[r] = 0.0f;
    float cc = 0.0f;
    __syncthreads();

    const float* xgb = xg + (size_t)b * TT * 512 + dir * 256 + r;
    const int t0 = dir ? (TT - 1) : 0;
    float xt = __ldg(xgb + (size_t)t0 * 512);

    for (int s = 0; s < TT; s++) {
        const int t = dir ? (TT - 1 - s) : s;
        float xnext = 0.0f;
        if (s + 1 < TT) {
            const int tn = dir ? (TT - 2 - s) : (s + 1);
            xnext = __ldg(xgb + (size_t)tn * 512);
        }

        ull acc = 0ull;
        #pragma unroll
        for (int kp = 0; kp < 32; kp++)
            fma2(acc, sW2[kp * 256 + r], *(const ull*)(sh + 2 * kp));
        float alo, ahi; upk(acc, alo, ahi);
        float v = xt + alo + ahi;
        sg[r] = (gate == 2) ? mytanh(v) : mysig(v);
        __syncthreads();

        if (r < 64) {
            float i_ = sg[j];
            float f_ = sg[j + 64];
            float gg = sg[j + 128];
            float o_ = sg[j + 192];
            cc = fmaf(f_, cc, i_ * gg);
            float h = o_ * mytanh(cc);
            sh[j] = h;
            y2[((size_t)b * TT + t) * 128 + dir * 64 + j] = h;
        }
        __syncthreads();
        xt = xnext;
    }
}

// =========================================================================
// Layer 3 recurrence + time mean: H=16, 4H=64. One WARP per (b,dir) chain,
// 2 gate rows per lane, shfl-based gate exchange, __syncwarp only.
// grid 64, 256 threads (8 chains per CTA).
// =========================================================================
__global__ __launch_bounds__(256, 1) void lstm3_kernel(
    const float* __restrict__ xg,    // (B*T, 128)
    const float* __restrict__ Whh,   // (2,64,16)
    float* __restrict__ s3)          // (B,32) mean
{
    __shared__ float shh[8][16];
    const int tid = threadIdx.x;
    const int wid = tid >> 5;
    const int lane = tid & 31;
    const int pg = blockIdx.x * 8 + wid;
    const int b = pg >> 1;
    const int dir = pg & 1;
    const int r0 = lane;        // rows 0..31  (gates i, f)
    const int r1 = lane + 32;   // rows 32..63 (gates g, o)
    const float* WhhD = Whh + (size_t)dir * 64 * 16;
    float* shp = shh[wid];

    ull w0[8], w1[8];
    #pragma unroll
    for (int kp = 0; kp < 8; kp++) {
        w0[kp] = *(const ull*)(WhhD + r0 * 16 + 2 * kp);
        w1[kp] = *(const ull*)(WhhD + r1 * 16 + 2 * kp);
    }

    if (lane < 16) shp[lane] = 0.0f;
    float cc = 0.0f, sum = 0.0f;
    __syncwarp();

    const float* xgb = xg + (size_t)b * TT * 128 + dir * 64;
    const int t0 = dir ? (TT - 1) : 0;
    float xt0 = __ldg(xgb + (size_t)t0 * 128 + r0);
    float xt1 = __ldg(xgb + (size_t)t0 * 128 + r1);

    for (int s = 0; s < TT; s++) {
        float xn0 = 0.0f, xn1 = 0.0f;
        if (s + 1 < TT) {
            const int tn = dir ? (TT - 2 - s) : (s + 1);
            xn0 = __ldg(xgb + (size_t)tn * 128 + r0);
            xn1 = __ldg(xgb + (size_t)tn * 128 + r1);
        }

        ull acc0 = 0ull, acc1 = 0ull;
        #pragma unroll
        for (int kp = 0; kp < 8; kp++) {
            ull hb = *(const ull*)(shp + 2 * kp);
            fma2(acc0, w0[kp], hb);
            fma2(acc1, w1[kp], hb);
        }
        float l0, h0, l1, h1;
        upk(acc0, l0, h0); upk(acc1, l1, h1);
        float v0 = xt0 + l0 + h0;
        float v1 = xt1 + l1 + h1;

        float a0 = mysig(v0);                               // i (lane<16) / f
        float a1 = (lane < 16) ? mytanh(v1) : mysig(v1);    // g (lane<16) / o
        float f_ = __shfl_down_sync(0xffffffffu, a0, 16);
        float o_ = __shfl_down_sync(0xffffffffu, a1, 16);
        if (lane < 16) {
            cc = fmaf(f_, cc, a0 * a1);
            float h = o_ * mytanh(cc);
            shp[lane] = h;
            sum += h;
        }
        __syncwarp();
        xt0 = xn0; xt1 = xn1;
    }
    if (lane < 16) s3[b * 32 + dir * 16 + lane] = sum * (1.0f / TT);
}

// =========================================================================
// MLP head: (256,32) -> 64 relu -> 16 relu -> 20. One thread per batch.
// =========================================================================
__global__ void mlp_kernel(
    const float* __restrict__ s3,
    const float* __restrict__ hW1, const float* __restrict__ hb1,
    const float* __restrict__ hW2, const float* __restrict__ hb2,
    const float* __restrict__ hW3, const float* __restrict__ hb3,
    float* __restrict__ out)
{
    int b = blockIdx.x * blockDim.x + threadIdx.x;
    if (b >= BB) return;
    float s[32];
    #pragma unroll
    for (int k = 0; k < 32; k++) s[k] = s3[b * 32 + k];
    float h1[64];
    for (int o = 0; o < 64; o++) {
        float a = hb1[o];
        #pragma unroll
        for (int k = 0; k < 32; k++) a = fmaf(s[k], hW1[o * 32 + k], a);
        h1[o] = fmaxf(a, 0.0f);
    }
    float h2[16];
    for (int o = 0; o < 16; o++) {
        float a = hb2[o];
        #pragma unroll
        for (int k = 0; k < 64; k++) a = fmaf(h1[k], hW2[o * 64 + k], a);
        h2[o] = fmaxf(a, 0.0f);
    }
    for (int o = 0; o < 20; o++) {
        float a = hb3[o];
        #pragma unroll
        for (int k = 0; k < 16; k++) a = fmaf(h2[k], hW3[o * 16 + k], a);
        out[b * 20 + o] = a;
    }
}

// =========================================================================
extern "C" void kernel_launch(void* const* d_in, const int* in_sizes, int n_in,
                              void* d_out, int out_size)
{
    const float* x    = (const float*)d_in[0];
    const float* Wih1 = (const float*)d_in[1];
    const float* Whh1 = (const float*)d_in[2];
    const float* bih1 = (const float*)d_in[3];
    const float* bhh1 = (const float*)d_in[4];
    const float* Wih2 = (const float*)d_in[5];
    const float* Whh2 = (const float*)d_in[6];
    const float* bih2 = (const float*)d_in[7];
    const float* bhh2 = (const float*)d_in[8];
    const float* Wih3 = (const float*)d_in[9];
    const float* Whh3 = (const float*)d_in[10];
    const float* bih3 = (const float*)d_in[11];
    const float* bhh3 = (const float*)d_in[12];
    const float* hW1  = (const float*)d_in[13];
    const float* hb1  = (const float*)d_in[14];
    const float* hW2  = (const float*)d_in[15];
    const float* hb2  = (const float*)d_in[16];
    const float* hW3  = (const float*)d_in[17];
    const float* hb3  = (const float*)d_in[18];
    float* out = (float*)d_out;

    float *y1, *xg2, *y2, *xg3, *s3;
    cudaGetSymbolAddress((void**)&y1,  g_y1);
    cudaGetSymbolAddress((void**)&xg2, g_xg2);
    cudaGetSymbolAddress((void**)&y2,  g_y2);
    cudaGetSymbolAddress((void**)&xg3, g_xg3);
    cudaGetSymbolAddress((void**)&s3,  g_sum3);

    static bool attr_set = false;
    if (!attr_set) {
        cudaFuncSetAttribute(lstm1_kernel,
            cudaFuncAttributeMaxDynamicSharedMemorySize, L1_SMEM_BYTES);
        cudaFuncSetAttribute(lstm2_kernel,
            cudaFuncAttributeMaxDynamicSharedMemorySize, L2_SMEM_BYTES);
        attr_set = true;
    }

    const int M = BB * TT;

    lstm1_kernel<<<dim3(64, 2), 512, L1_SMEM_BYTES>>>(x, Wih1, Whh1, bih1, bhh1, y1);
    gemm_bias_kernel<<<dim3(512 / 64, M / 128), 256>>>(y1, Wih2, bih2, bhh2, xg2, 512, 256);
    lstm2_kernel<<<512, 256, L2_SMEM_BYTES>>>(xg2, Whh2, y2);
    gemm_bias_kernel<<<dim3(128 / 64, M / 128), 256>>>(y2, Wih3, bih3, bhh3, xg3, 128, 128);
    lstm3_kernel<<<64, 256>>>(xg3, Whh3, s3);
    mlp_kernel<<<1, 256>>>(s3, hW1, hb1, hW2, hb2, hW3, hb3, out);
}

// round 7
// speedup vs baseline: 1.0827x; 1.0001x over previous
#include <cuda_runtime.h>
#include <math.h>

#define BB 256
#define TT 2048

// ---------------- scratch (static device memory; no allocations) ----------------
__device__ float g_y1 [(size_t)BB * TT * 256];   // layer1 output (B,T,256)
__device__ float g_xg2[(size_t)BB * TT * 512];   // layer2 input gates
__device__ float g_y2 [(size_t)BB * TT * 128];   // layer2 output (B,T,128)
__device__ float g_xg3[(size_t)BB * TT * 128];   // layer3 input gates
__device__ float g_sum3[BB * 32];                // time-mean of layer3 output

typedef unsigned long long ull;

// ---- fast helpers -------------------------------------------------------
__device__ __forceinline__ float mysig(float v) {
    return __fdividef(1.0f, 1.0f + __expf(-v));
}
__device__ __forceinline__ float mytanh(float v) {
    // 1 - 2/(1+e^{2v}); saturates correctly for |v| large, no NaN path
    float e = __expf(2.0f * v);
    return 1.0f - 2.0f * __fdividef(1.0f, 1.0f + e);
}
__device__ __forceinline__ ull pk(float lo, float hi) {
    ull r; asm("mov.b64 %0, {%1, %2};" : "=l"(r) : "f"(lo), "f"(hi)); return r;
}
__device__ __forceinline__ void upk(ull v, float& lo, float& hi) {
    asm("mov.b64 {%0, %1}, %2;" : "=f"(lo), "=f"(hi) : "l"(v));
}
__device__ __forceinline__ void fma2(ull& d, ull a, ull b) {
    asm("fma.rn.f32x2 %0, %1, %2, %0;" : "+l"(d) : "l"(a), "l"(b));
}

// =========================================================================
// Layer 1: fused x-projection (D=2) + recurrence. H=128, 4H=512.
// grid (64, 2). 512 threads: thread r owns gate row r for 4 batches.
// Whh row: 64 k in regs + 64 k in k-major smem. h stored [k][4b] so one
// LDS.128 yields both packed f32x2 batch-pairs.
// =========================================================================
#define L1_KREG 64
#define L1_KS   64
#define L1_SMEM_BYTES ((L1_KS * 512 + 128 * 4 + 4 * 512) * 4)

__global__ __launch_bounds__(512, 1) void lstm1_kernel(
    const float* __restrict__ x,     // (256,2048,2)
    const float* __restrict__ Wih,   // (2,512,2)
    const float* __restrict__ Whh,   // (2,512,128)
    const float* __restrict__ bih,   // (2,512)
    const float* __restrict__ bhh,   // (2,512)
    float* __restrict__ y1)          // (256,2048,256)
{
    extern __shared__ float sm[];
    float* sWk = sm;                    // [64][512] k-major, k in [64,128)
    float* sh4 = sm + L1_KS * 512;      // [128 k][4 b]
    float* sg  = sh4 + 128 * 4;         // [4 b][512 r]

    const int dir = blockIdx.y;
    const int bg0 = blockIdx.x * 4;
    const int r   = threadIdx.x;
    const float* WhhD = Whh + (size_t)dir * 512 * 128;

    for (int i = r; i < L1_KS * 512; i += 512) {
        int kk = i >> 9, rr = i & 511;
        sWk[i] = WhhD[rr * 128 + L1_KREG + kk];
    }
    float Wreg[L1_KREG];
    #pragma unroll
    for (int k = 0; k < L1_KREG; k++) Wreg[k] = WhhD[r * 128 + k];

    const float wx0  = Wih[dir * 1024 + r * 2 + 0];
    const float wx1  = Wih[dir * 1024 + r * 2 + 1];
    const float bias = bih[dir * 512 + r] + bhh[dir * 512 + r];
    const int   gate = r >> 7;          // 0=i 1=f 2=g 3=o
    const int   cb = r >> 7;            // combine: batch
    const int   j  = r & 127;           // combine: unit

    sh4[r] = 0.0f;                      // 512 entries, all threads
    float cc = 0.0f;
    __syncthreads();

    for (int s = 0; s < TT; s++) {
        const int t = dir ? (TT - 1 - s) : s;
        float2 xv0 = __ldg((const float2*)(x + ((size_t)(bg0 + 0) * TT + t) * 2));
        float2 xv1 = __ldg((const float2*)(x + ((size_t)(bg0 + 1) * TT + t) * 2));
        float2 xv2 = __ldg((const float2*)(x + ((size_t)(bg0 + 2) * TT + t) * 2));
        float2 xv3 = __ldg((const float2*)(x + ((size_t)(bg0 + 3) * TT + t) * 2));

        ull acc01 = 0ull, acc23 = 0ull;   // {0.f,0.f}
        #pragma unroll
        for (int k = 0; k < L1_KREG; k++) {
            ulonglong2 hb = *(const ulonglong2*)(sh4 + k * 4);  // broadcast
            ull wd = pk(Wreg[k], Wreg[k]);
            fma2(acc01, wd, hb.x);
            fma2(acc23, wd, hb.y);
        }
        #pragma unroll
        for (int kk = 0; kk < L1_KS; kk++) {
            const int k = L1_KREG + kk;
            float w = sWk[kk * 512 + r];
            ulonglong2 hb = *(const ulonglong2*)(sh4 + k * 4);
            ull wd = pk(w, w);
            fma2(acc01, wd, hb.x);
            fma2(acc23, wd, hb.y);
        }

        float a0, a1, a2, a3;
        upk(acc01, a0, a1); upk(acc23, a2, a3);
        float v0 = fmaf(wx0, xv0.x, fmaf(wx1, xv0.y, bias + a0));
        float v1 = fmaf(wx0, xv1.x, fmaf(wx1, xv1.y, bias + a1));
        float v2 = fmaf(wx0, xv2.x, fmaf(wx1, xv2.y, bias + a2));
        float v3 = fmaf(wx0, xv3.x, fmaf(wx1, xv3.y, bias + a3));
        if (gate == 2) {
            sg[0*512 + r] = mytanh(v0); sg[1*512 + r] = mytanh(v1);
            sg[2*512 + r] = mytanh(v2); sg[3*512 + r] = mytanh(v3);
        } else {
            sg[0*512 + r] = mysig(v0); sg[1*512 + r] = mysig(v1);
            sg[2*512 + r] = mysig(v2); sg[3*512 + r] = mysig(v3);
        }
        __syncthreads();

        // combine: thread handles (batch cb, unit j)
        {
            float i_ = sg[cb*512 + j];
            float f_ = sg[cb*512 + j + 128];
            float gg = sg[cb*512 + j + 256];
            float o_ = sg[cb*512 + j + 384];
            cc = fmaf(f_, cc, i_ * gg);
            float h = o_ * mytanh(cc);
            sh4[j * 4 + cb] = h;
            y1[((size_t)(bg0 + cb) * TT + t) * 256 + dir * 128 + j] = h;
        }
        __syncthreads();
    }
}

// =========================================================================
// Tiled fp32 GEMM + bias: C[m][n] = sum_k A[m][k]*B[n][k] + b1[n] + b2[n]
// BM=128, BN=64, BK=16, 256 threads, 8x4 microtile.
// =========================================================================
__global__ __launch_bounds__(256) void gemm_bias_kernel(
    const float* __restrict__ A, const float* __restrict__ B,
    const float* __restrict__ b1, const float* __restrict__ b2,
    float* __restrict__ C, int N, int K)
{
    __shared__ float As[16][128];
    __shared__ float Bs[16][64];
    const int m0 = blockIdx.y * 128;
    const int n0 = blockIdx.x * 64;
    const int tid = threadIdx.x;
    const int tx = tid & 15, ty = tid >> 4;
    const int lrow = tid >> 2;
    const int lcol = (tid & 3) << 2;

    float acc[8][4];
    #pragma unroll
    for (int i = 0; i < 8; i++)
        #pragma unroll
        for (int jj = 0; jj < 4; jj++) acc[i][jj] = 0.0f;

    for (int k0 = 0; k0 < K; k0 += 16) {
        #pragma unroll
        for (int rr = 0; rr < 2; rr++) {
            int row = lrow + rr * 64;
            float4 v = *(const float4*)&A[(size_t)(m0 + row) * K + k0 + lcol];
            As[lcol+0][row] = v.x; As[lcol+1][row] = v.y;
            As[lcol+2][row] = v.z; As[lcol+3][row] = v.w;
        }
        {
            float4 v = *(const float4*)&B[(size_t)(n0 + lrow) * K + k0 + lcol];
            Bs[lcol+0][lrow] = v.x; Bs[lcol+1][lrow] = v.y;
            Bs[lcol+2][lrow] = v.z; Bs[lcol+3][lrow] = v.w;
        }
        __syncthreads();
        #pragma unroll
        for (int k = 0; k < 16; k++) {
            float4 av0 = *(const float4*)&As[k][ty * 8];
            float4 av1 = *(const float4*)&As[k][ty * 8 + 4];
            float4 bv = *(const float4*)&Bs[k][tx * 4];
            float ar[8] = {av0.x, av0.y, av0.z, av0.w, av1.x, av1.y, av1.z, av1.w};
            float br[4] = {bv.x, bv.y, bv.z, bv.w};
            #pragma unroll
            for (int i = 0; i < 8; i++)
                #pragma unroll
                for (int jj = 0; jj < 4; jj++)
                    acc[i][jj] = fmaf(ar[i], br[jj], acc[i][jj]);
        }
        __syncthreads();
    }
    #pragma unroll
    for (int i = 0; i < 8; i++) {
        size_t row = (size_t)(m0 + ty * 8 + i);
        #pragma unroll
        for (int jj = 0; jj < 4; jj++) {
            int col = n0 + tx * 4 + jj;
            C[row * N + col] = acc[i][jj] + b1[col] + b2[col];
        }
    }
}

// =========================================================================
// Layer 2 recurrence: H=64, 4H=256. 256 threads, CTA = one (b,dir) chain.
// Weights in 64 KB dynamic smem, pre-packed as f32x2 k-pairs: sW2[kp][r].
// xt prefetched one step ahead. grid 512, ~3 CTAs/SM.
// =========================================================================
#define L2_SMEM_BYTES (32 * 256 * 8 + 64 * 4 + 256 * 4)

__global__ __launch_bounds__(256, 1) void lstm2_kernel(
    const float* __restrict__ xg,    // (B*T, 512)
    const float* __restrict__ Whh,   // (2,256,64)
    float* __restrict__ y2)          // (B,T,128)
{
    extern __shared__ char smraw[];
    ull*   sW2 = (ull*)smraw;                     // [32 kp][256 r]
    float* sh  = (float*)(smraw + 32 * 256 * 8);  // [64]
    float* sg  = sh + 64;                         // [256]

    const int r = threadIdx.x;
    const int b   = blockIdx.x >> 1;
    const int dir = blockIdx.x & 1;
    const int gate = r >> 6;
    const int j = r & 63;
    const float* WhhD = Whh + (size_t)dir * 256 * 64;

    for (int i = r; i < 32 * 256; i += 256) {
        int kp = i >> 8, rr = i & 255;
        sW2[i] = *(const ull*)(WhhD + rr * 64 + 2 * kp);
    }
    if (r < 64) sh[r] = 0.0f;
    float cc = 0.0f;
    __syncthreads();

    const float* xgb = xg + (size_t)b * TT * 512 + dir * 256 + r;
    const int t0 = dir ? (TT - 1) : 0;
    float xt = __ldg(xgb + (size_t)t0 * 512);

    for (int s = 0; s < TT; s++) {
        const int t = dir ? (TT - 1 - s) : s;
        float xnext = 0.0f;
        if (s + 1 < TT) {
            const int tn = dir ? (TT - 2 - s) : (s + 1);
            xnext = __ldg(xgb + (size_t)tn * 512);
        }

        ull acc = 0ull;
        #pragma unroll
        for (int kp = 0; kp < 32; kp++)
            fma2(acc, sW2[kp * 256 + r], *(const ull*)(sh + 2 * kp));
        float alo, ahi; upk(acc, alo, ahi);
        float v = xt + alo + ahi;
        sg[r] = (gate == 2) ? mytanh(v) : mysig(v);
        __syncthreads();

        if (r < 64) {
            float i_ = sg[j];
            float f_ = sg[j + 64];
            float gg = sg[j + 128];
            float o_ = sg[j + 192];
            cc = fmaf(f_, cc, i_ * gg);
            float h = o_ * mytanh(cc);
            sh[j] = h;
            y2[((size_t)b * TT + t) * 128 + dir * 64 + j] = h;
        }
        __syncthreads();
        xt = xnext;
    }
}

// =========================================================================
// Layer 3 recurrence + time mean: H=16, 4H=64. One WARP per (b,dir) chain,
// 2 gate rows per lane, shfl-based gate exchange, __syncwarp only.
// grid 64, 256 threads (8 chains per CTA).
// =========================================================================
__global__ __launch_bounds__(256, 1) void lstm3_kernel(
    const float* __restrict__ xg,    // (B*T, 128)
    const float* __restrict__ Whh,   // (2,64,16)
    float* __restrict__ s3)          // (B,32) mean
{
    __shared__ float shh[8][16];
    const int tid = threadIdx.x;
    const int wid = tid >> 5;
    const int lane = tid & 31;
    const int pg = blockIdx.x * 8 + wid;
    const int b = pg >> 1;
    const int dir = pg & 1;
    const int r0 = lane;        // rows 0..31  (gates i, f)
    const int r1 = lane + 32;   // rows 32..63 (gates g, o)
    const float* WhhD = Whh + (size_t)dir * 64 * 16;
    float* shp = shh[wid];

    ull w0[8], w1[8];
    #pragma unroll
    for (int kp = 0; kp < 8; kp++) {
        w0[kp] = *(const ull*)(WhhD + r0 * 16 + 2 * kp);
        w1[kp] = *(const ull*)(WhhD + r1 * 16 + 2 * kp);
    }

    if (lane < 16) shp[lane] = 0.0f;
    float cc = 0.0f, sum = 0.0f;
    __syncwarp();

    const float* xgb = xg + (size_t)b * TT * 128 + dir * 64;
    const int t0 = dir ? (TT - 1) : 0;
    float xt0 = __ldg(xgb + (size_t)t0 * 128 + r0);
    float xt1 = __ldg(xgb + (size_t)t0 * 128 + r1);

    for (int s = 0; s < TT; s++) {
        float xn0 = 0.0f, xn1 = 0.0f;
        if (s + 1 < TT) {
            const int tn = dir ? (TT - 2 - s) : (s + 1);
            xn0 = __ldg(xgb + (size_t)tn * 128 + r0);
            xn1 = __ldg(xgb + (size_t)tn * 128 + r1);
        }

        ull acc0 = 0ull, acc1 = 0ull;
        #pragma unroll
        for (int kp = 0; kp < 8; kp++) {
            ull hb = *(const ull*)(shp + 2 * kp);
            fma2(acc0, w0[kp], hb);
            fma2(acc1, w1[kp], hb);
        }
        float l0, h0, l1, h1;
        upk(acc0, l0, h0); upk(acc1, l1, h1);
        float v0 = xt0 + l0 + h0;
        float v1 = xt1 + l1 + h1;

        float a0 = mysig(v0);                               // i (lane<16) / f
        float a1 = (lane < 16) ? mytanh(v1) : mysig(v1);    // g (lane<16) / o
        float f_ = __shfl_down_sync(0xffffffffu, a0, 16);
        float o_ = __shfl_down_sync(0xffffffffu, a1, 16);
        if (lane < 16) {
            cc = fmaf(f_, cc, a0 * a1);
            float h = o_ * mytanh(cc);
            shp[lane] = h;
            sum += h;
        }
        __syncwarp();
        xt0 = xn0; xt1 = xn1;
    }
    if (lane < 16) s3[b * 32 + dir * 16 + lane] = sum * (1.0f / TT);
}

// =========================================================================
// MLP head: (256,32) -> 64 relu -> 16 relu -> 20. One thread per batch.
// =========================================================================
__global__ void mlp_kernel(
    const float* __restrict__ s3,
    const float* __restrict__ hW1, const float* __restrict__ hb1,
    const float* __restrict__ hW2, const float* __restrict__ hb2,
    const float* __restrict__ hW3, const float* __restrict__ hb3,
    float* __restrict__ out)
{
    int b = blockIdx.x * blockDim.x + threadIdx.x;
    if (b >= BB) return;
    float s[32];
    #pragma unroll
    for (int k = 0; k < 32; k++) s[k] = s3[b * 32 + k];
    float h1[64];
    for (int o = 0; o < 64; o++) {
        float a = hb1[o];
        #pragma unroll
        for (int k = 0; k < 32; k++) a = fmaf(s[k], hW1[o * 32 + k], a);
        h1[o] = fmaxf(a, 0.0f);
    }
    float h2[16];
    for (int o = 0; o < 16; o++) {
        float a = hb2[o];
        #pragma unroll
        for (int k = 0; k < 64; k++) a = fmaf(h1[k], hW2[o * 64 + k], a);
        h2[o] = fmaxf(a, 0.0f);
    }
    for (int o = 0; o < 20; o++) {
        float a = hb3[o];
        #pragma unroll
        for (int k = 0; k < 16; k++) a = fmaf(h2[k], hW3[o * 16 + k], a);
        out[b * 20 + o] = a;
    }
}

// =========================================================================
extern "C" void kernel_launch(void* const* d_in, const int* in_sizes, int n_in,
                              void* d_out, int out_size)
{
    const float* x    = (const float*)d_in[0];
    const float* Wih1 = (const float*)d_in[1];
    const float* Whh1 = (const float*)d_in[2];
    const float* bih1 = (const float*)d_in[3];
    const float* bhh1 = (const float*)d_in[4];
    const float* Wih2 = (const float*)d_in[5];
    const float* Whh2 = (const float*)d_in[6];
    const float* bih2 = (const float*)d_in[7];
    const float* bhh2 = (const float*)d_in[8];
    const float* Wih3 = (const float*)d_in[9];
    const float* Whh3 = (const float*)d_in[10];
    const float* bih3 = (const float*)d_in[11];
    const float* bhh3 = (const float*)d_in[12];
    const float* hW1  = (const float*)d_in[13];
    const float* hb1  = (const float*)d_in[14];
    const float* hW2  = (const float*)d_in[15];
    const float* hb2  = (const float*)d_in[16];
    const float* hW3  = (const float*)d_in[17];
    const float* hb3  = (const float*)d_in[18];
    float* out = (float*)d_out;

    float *y1, *xg2, *y2, *xg3, *s3;
    cudaGetSymbolAddress((void**)&y1,  g_y1);
    cudaGetSymbolAddress((void**)&xg2, g_xg2);
    cudaGetSymbolAddress((void**)&y2,  g_y2);
    cudaGetSymbolAddress((void**)&xg3, g_xg3);
    cudaGetSymbolAddress((void**)&s3,  g_sum3);

    static bool attr_set = false;
    if (!attr_set) {
        cudaFuncSetAttribute(lstm1_kernel,
            cudaFuncAttributeMaxDynamicSharedMemorySize, L1_SMEM_BYTES);
        cudaFuncSetAttribute(lstm2_kernel,
            cudaFuncAttributeMaxDynamicSharedMemorySize, L2_SMEM_BYTES);
        attr_set = true;
    }

    const int M = BB * TT;

    lstm1_kernel<<<dim3(64, 2), 512, L1_SMEM_BYTES>>>(x, Wih1, Whh1, bih1, bhh1, y1);
    gemm_bias_kernel<<<dim3(512 / 64, M / 128), 256>>>(y1, Wih2, bih2, bhh2, xg2, 512, 256);
    lstm2_kernel<<<512, 256, L2_SMEM_BYTES>>>(xg2, Whh2, y2);
    gemm_bias_kernel<<<dim3(128 / 64, M / 128), 256>>>(y2, Wih3, bih3, bhh3, xg3, 128, 128);
    lstm3_kernel<<<64, 256>>>(xg3, Whh3, s3);
    mlp_kernel<<<1, 256>>>(s3, hW1, hb1, hW2, hb2, hW3, hb3, out);
}

// round 9
// speedup vs baseline: 1.0981x; 1.0142x over previous
#include <cuda_runtime.h>
#include <math.h>

#define BB 256
#define TT 2048
typedef unsigned long long ull;

__device__ float g_y1 [(size_t)BB * TT * 256];
__device__ float g_xg2[(size_t)BB * TT * 512];
__device__ float g_y2 [(size_t)BB * TT * 128];
__device__ float g_xg3[(size_t)BB * TT * 128];
__device__ float g_sum3[BB * 32];

__device__ __forceinline__ float mysig(float v){ return __fdividef(1.0f, 1.0f + __expf(-v)); }
__device__ __forceinline__ float mytanh(float v){
    float e = __expf(2.0f * v);
    return 1.0f - 2.0f * __fdividef(1.0f, 1.0f + e);
}
__device__ __forceinline__ ull pk(float lo, float hi){
    ull r; asm("mov.b64 %0, {%1, %2};" : "=l"(r) : "f"(lo), "f"(hi)); return r;
}
__device__ __forceinline__ void upk(ull v, float& lo, float& hi){
    asm("mov.b64 {%0, %1}, %2;" : "=f"(lo), "=f"(hi) : "l"(v));
}
__device__ __forceinline__ void fma2(ull& d, ull a, ull b){
    asm("fma.rn.f32x2 %0, %1, %2, %0;" : "+l"(d) : "l"(a), "l"(b));
}

// =========================================================================
// Layer 1: H=128, 4H=512, D=2 fused. grid (64,2), 512 threads.
// Thread r owns gate row r for 4 batches. f32x2 accumulation over k-pairs:
// weights pre-packed as ull k-pairs (32 in regs, 32 in smem), h stored
// [kp][4b] so LDS.128 broadcasts feed fma.rn.f32x2 directly (no per-step
// packing). Per-thread ~420 instrs / 2048 MACs per step.
// =========================================================================
#define L1_SWP  0                      // ull [32][512]  = 131072 B
#define L1_H4   131072                 // ull [64][4]    = 2048 B
#define L1_GAT  133120                 // float [4][512] = 8192 B
#define L1_SMEM 141312

__global__ __launch_bounds__(512, 1) void lstm1_kernel(
    const float* __restrict__ x, const float* __restrict__ Wih,
    const float* __restrict__ Whh, const float* __restrict__ bih,
    const float* __restrict__ bhh, float* __restrict__ y1)
{
    extern __shared__ char smraw[];
    ull*   sWp = (ull*)(smraw + L1_SWP);    // [32 kp][512 r]
    ull*   sh4 = (ull*)(smraw + L1_H4);     // [64 kp][4 b]
    float* sg  = (float*)(smraw + L1_GAT);  // [4 b][512 r]
    float* sh4f = (float*)sh4;

    const int dir = blockIdx.y, bg0 = blockIdx.x * 4;
    const int r = threadIdx.x;
    const float* WD = Whh + (size_t)dir * 512 * 128;

    ull Wreg[32];
    #pragma unroll
    for (int kp = 0; kp < 32; kp++)
        Wreg[kp] = pk(WD[r * 128 + 2 * kp], WD[r * 128 + 2 * kp + 1]);
    for (int kp = 0; kp < 32; kp++)
        sWp[kp * 512 + r] = pk(WD[r * 128 + 64 + 2 * kp], WD[r * 128 + 65 + 2 * kp]);

    const float wx0  = Wih[dir * 1024 + r * 2];
    const float wx1  = Wih[dir * 1024 + r * 2 + 1];
    const float bias = bih[dir * 512 + r] + bhh[dir * 512 + r];
    const int gate = r >> 7;
    const int cb = r >> 7, j = r & 127;     // combine role
    float cc = 0.0f;

    if (r < 256) sh4[r] = 0ull;
    __syncthreads();

    for (int s = 0; s < TT; s++) {
        const int t = dir ? (TT - 1 - s) : s;
        float2 xv0 = __ldg((const float2*)(x + ((size_t)(bg0 + 0) * TT + t) * 2));
        float2 xv1 = __ldg((const float2*)(x + ((size_t)(bg0 + 1) * TT + t) * 2));
        float2 xv2 = __ldg((const float2*)(x + ((size_t)(bg0 + 2) * TT + t) * 2));
        float2 xv3 = __ldg((const float2*)(x + ((size_t)(bg0 + 3) * TT + t) * 2));

        ull a0 = 0ull, a1 = 0ull, a2 = 0ull, a3 = 0ull;
        #pragma unroll
        for (int kp = 0; kp < 32; kp++) {
            ulonglong2 p0 = *(const ulonglong2*)(sh4 + kp * 4);
            ulonglong2 p1 = *(const ulonglong2*)(sh4 + kp * 4 + 2);
            fma2(a0, Wreg[kp], p0.x);
            fma2(a1, Wreg[kp], p0.y);
            fma2(a2, Wreg[kp], p1.x);
            fma2(a3, Wreg[kp], p1.y);
        }
        #pragma unroll
        for (int kp = 0; kp < 32; kp++) {
            ull w = sWp[kp * 512 + r];
            ulonglong2 p0 = *(const ulonglong2*)(sh4 + (kp + 32) * 4);
            ulonglong2 p1 = *(const ulonglong2*)(sh4 + (kp + 32) * 4 + 2);
            fma2(a0, w, p0.x);
            fma2(a1, w, p0.y);
            fma2(a2, w, p1.x);
            fma2(a3, w, p1.y);
        }

        float l0, h0, l1, h1, l2, h2, l3, h3;
        upk(a0, l0, h0); upk(a1, l1, h1); upk(a2, l2, h2); upk(a3, l3, h3);
        float v0 = fmaf(wx0, xv0.x, fmaf(wx1, xv0.y, bias + l0 + h0));
        float v1 = fmaf(wx0, xv1.x, fmaf(wx1, xv1.y, bias + l1 + h1));
        float v2 = fmaf(wx0, xv2.x, fmaf(wx1, xv2.y, bias + l2 + h2));
        float v3 = fmaf(wx0, xv3.x, fmaf(wx1, xv3.y, bias + l3 + h3));
        if (gate == 2) {
            sg[0*512 + r] = mytanh(v0); sg[1*512 + r] = mytanh(v1);
            sg[2*512 + r] = mytanh(v2); sg[3*512 + r] = mytanh(v3);
        } else {
            sg[0*512 + r] = mysig(v0); sg[1*512 + r] = mysig(v1);
            sg[2*512 + r] = mysig(v2); sg[3*512 + r] = mysig(v3);
        }
        __syncthreads();

        {
            float i_ = sg[cb*512 + j];
            float f_ = sg[cb*512 + j + 128];
            float gg = sg[cb*512 + j + 256];
            float o_ = sg[cb*512 + j + 384];
            cc = fmaf(f_, cc, i_ * gg);
            float h = o_ * mytanh(cc);
            y1[((size_t)(bg0 + cb) * TT + t) * 256 + dir * 128 + j] = h;
            sh4f[(j >> 1) * 8 + cb * 2 + (j & 1)] = h;
        }
        __syncthreads();
    }
}

// ============ fp32 GEMM + bias: BM=BN=128, BK=16, 256 thr, 8x8 ============
__global__ __launch_bounds__(256) void gemm_bias_kernel(
    const float* __restrict__ A, const float* __restrict__ B,
    const float* __restrict__ b1, const float* __restrict__ b2,
    float* __restrict__ C, int N, int K)
{
    __shared__ float As[16][128];
    __shared__ float Bs[16][128];
    const int m0 = blockIdx.y * 128, n0 = blockIdx.x * 128;
    const int tid = threadIdx.x;
    const int tx = tid & 15, ty = tid >> 4;

    float acc[8][8];
    #pragma unroll
    for (int i = 0; i < 8; i++)
        #pragma unroll
        for (int jj = 0; jj < 8; jj++) acc[i][jj] = 0.0f;

    for (int k0 = 0; k0 < K; k0 += 16) {
        #pragma unroll
        for (int i = 0; i < 2; i++) {
            int id = tid * 2 + i;
            int row = id >> 2, c4 = (id & 3) * 4;
            float4 v = *(const float4*)&A[(size_t)(m0 + row) * K + k0 + c4];
            As[c4+0][row] = v.x; As[c4+1][row] = v.y; As[c4+2][row] = v.z; As[c4+3][row] = v.w;
            float4 w = *(const float4*)&B[(size_t)(n0 + row) * K + k0 + c4];
            Bs[c4+0][row] = w.x; Bs[c4+1][row] = w.y; Bs[c4+2][row] = w.z; Bs[c4+3][row] = w.w;
        }
        __syncthreads();
        #pragma unroll
        for (int k = 0; k < 16; k++) {
            float ar[8], br[8];
            *(float4*)(ar)   = *(const float4*)&As[k][ty * 8];
            *(float4*)(ar+4) = *(const float4*)&As[k][ty * 8 + 4];
            *(float4*)(br)   = *(const float4*)&Bs[k][tx * 8];
            *(float4*)(br+4) = *(const float4*)&Bs[k][tx * 8 + 4];
            #pragma unroll
            for (int i = 0; i < 8; i++)
                #pragma unroll
                for (int jj = 0; jj < 8; jj++)
                    acc[i][jj] = fmaf(ar[i], br[jj], acc[i][jj]);
        }
        __syncthreads();
    }
    float bb[8];
    #pragma unroll
    for (int jj = 0; jj < 8; jj++) { int c = n0 + tx * 8 + jj; bb[jj] = b1[c] + b2[c]; }
    #pragma unroll
    for (int i = 0; i < 8; i++) {
        size_t row = (size_t)(m0 + ty * 8 + i);
        float4 o0 = {acc[i][0]+bb[0], acc[i][1]+bb[1], acc[i][2]+bb[2], acc[i][3]+bb[3]};
        float4 o1 = {acc[i][4]+bb[4], acc[i][5]+bb[5], acc[i][6]+bb[6], acc[i][7]+bb[7]};
        *(float4*)&C[row * N + n0 + tx * 8]     = o0;
        *(float4*)&C[row * N + n0 + tx * 8 + 4] = o1;
    }
}

// ============ Layer 2: H=64. CTA = one (b,dir) chain, 256 thr ============
#define L2_SMEM_BYTES (32 * 256 * 8 + 64 * 4 + 256 * 4)
__global__ __launch_bounds__(256, 1) void lstm2_kernel(
    const float* __restrict__ xg, const float* __restrict__ Whh,
    float* __restrict__ y2)
{
    extern __shared__ char smraw[];
    ull*   sW2 = (ull*)smraw;
    float* sh  = (float*)(smraw + 32 * 256 * 8);
    float* sg  = sh + 64;
    const int r = threadIdx.x;
    const int b = blockIdx.x >> 1, dir = blockIdx.x & 1;
    const int gate = r >> 6, j = r & 63;
    const float* WhhD = Whh + (size_t)dir * 256 * 64;

    for (int i = r; i < 32 * 256; i += 256) {
        int kp = i >> 8, rr = i & 255;
        sW2[i] = *(const ull*)(WhhD + rr * 64 + 2 * kp);
    }
    if (r < 64) sh[r] = 0.0f;
    float cc = 0.0f;
    __syncthreads();

    const float* xgb = xg + (size_t)b * TT * 512 + dir * 256 + r;
    const int t0 = dir ? (TT - 1) : 0;
    float xt = __ldg(xgb + (size_t)t0 * 512);

    for (int s = 0; s < TT; s++) {
        const int t = dir ? (TT - 1 - s) : s;
        float xnext = 0.0f;
        if (s + 1 < TT) {
            const int tn = dir ? (TT - 2 - s) : (s + 1);
            xnext = __ldg(xgb + (size_t)tn * 512);
        }
        ull accA = 0ull, accB = 0ull;
        #pragma unroll
        for (int kp = 0; kp < 32; kp += 2) {
            fma2(accA, sW2[kp * 256 + r],       *(const ull*)(sh + 2 * kp));
            fma2(accB, sW2[(kp + 1) * 256 + r], *(const ull*)(sh + 2 * kp + 2));
        }
        float alo, ahi, blo, bhi;
        upk(accA, alo, ahi); upk(accB, blo, bhi);
        float v = xt + (alo + ahi) + (blo + bhi);
        sg[r] = (gate == 2) ? mytanh(v) : mysig(v);
        __syncthreads();
        if (r < 64) {
            float i_ = sg[j], f_ = sg[j+64], gg = sg[j+128], o_ = sg[j+192];
            cc = fmaf(f_, cc, i_ * gg);
            float h = o_ * mytanh(cc);
            sh[j] = h;
            y2[((size_t)b * TT + t) * 128 + dir * 64 + j] = h;
        }
        __syncthreads();
        xt = xnext;
    }
}

// ============ Layer 3 + mean: warp per chain, shfl exchange ============
__global__ __launch_bounds__(256, 1) void lstm3_kernel(
    const float* __restrict__ xg, const float* __restrict__ Whh,
    float* __restrict__ s3)
{
    __shared__ float shh[8][16];
    const int tid = threadIdx.x, wid = tid >> 5, lane = tid & 31;
    const int pg = blockIdx.x * 8 + wid;
    const int b = pg >> 1, dir = pg & 1;
    const int r0 = lane, r1 = lane + 32;
    const float* WhhD = Whh + (size_t)dir * 64 * 16;
    float* shp = shh[wid];

    ull w0[8], w1[8];
    #pragma unroll
    for (int kp = 0; kp < 8; kp++) {
        w0[kp] = *(const ull*)(WhhD + r0 * 16 + 2 * kp);
        w1[kp] = *(const ull*)(WhhD + r1 * 16 + 2 * kp);
    }
    if (lane < 16) shp[lane] = 0.0f;
    float cc = 0.0f, sum = 0.0f;
    __syncwarp();

    const float* xgb = xg + (size_t)b * TT * 128 + dir * 64;
    const int t0 = dir ? (TT - 1) : 0;
    float xt0 = __ldg(xgb + (size_t)t0 * 128 + r0);
    float xt1 = __ldg(xgb + (size_t)t0 * 128 + r1);

    for (int s = 0; s < TT; s++) {
        float xn0 = 0.0f, xn1 = 0.0f;
        if (s + 1 < TT) {
            const int tn = dir ? (TT - 2 - s) : (s + 1);
            xn0 = __ldg(xgb + (size_t)tn * 128 + r0);
            xn1 = __ldg(xgb + (size_t)tn * 128 + r1);
        }
        ull a0 = 0ull, a1 = 0ull;
        #pragma unroll
        for (int kp = 0; kp < 8; kp++) {
            ull hb = *(const ull*)(shp + 2 * kp);
            fma2(a0, w0[kp], hb);
            fma2(a1, w1[kp], hb);
        }
        float l0, h0, l1, h1;
        upk(a0, l0, h0); upk(a1, l1, h1);
        float v0 = xt0 + l0 + h0, v1 = xt1 + l1 + h1;
        float g0 = mysig(v0);
        float g1 = (lane < 16) ? mytanh(v1) : mysig(v1);
        float f_ = __shfl_down_sync(0xffffffffu, g0, 16);
        float o_ = __shfl_down_sync(0xffffffffu, g1, 16);
        if (lane < 16) {
            cc = fmaf(f_, cc, g0 * g1);
            float h = o_ * mytanh(cc);
            shp[lane] = h;
            sum += h;
        }
        __syncwarp();
        xt0 = xn0; xt1 = xn1;
    }
    if (lane < 16) s3[b * 32 + dir * 16 + lane] = sum * (1.0f / TT);
}

// ============ MLP head ============
__global__ void mlp_kernel(
    const float* __restrict__ s3,
    const float* __restrict__ hW1, const float* __restrict__ hb1,
    const float* __restrict__ hW2, const float* __restrict__ hb2,
    const float* __restrict__ hW3, const float* __restrict__ hb3,
    float* __restrict__ out)
{
    int b = blockIdx.x * blockDim.x + threadIdx.x;
    if (b >= BB) return;
    float s[32];
    #pragma unroll
    for (int k = 0; k < 32; k++) s[k] = s3[b * 32 + k];
    float h1[64];
    for (int o = 0; o < 64; o++) {
        float a = hb1[o];
        #pragma unroll
        for (int k = 0; k < 32; k++) a = fmaf(s[k], hW1[o * 32 + k], a);
        h1[o] = fmaxf(a, 0.0f);
    }
    float h2[16];
    for (int o = 0; o < 16; o++) {
        float a = hb2[o];
        #pragma unroll
        for (int k = 0; k < 64; k++) a = fmaf(h1[k], hW2[o * 64 + k], a);
        h2[o] = fmaxf(a, 0.0f);
    }
    for (int o = 0; o < 20; o++) {
        float a = hb3[o];
        #pragma unroll
        for (int k = 0; k < 16; k++) a = fmaf(h2[k], hW3[o * 16 + k], a);
        out[b * 20 + o] = a;
    }
}

extern "C" void kernel_launch(void* const* d_in, const int* in_sizes, int n_in,
                              void* d_out, int out_size)
{
    const float* x    = (const float*)d_in[0];
    const float* Wih1 = (const float*)d_in[1];
    const float* Whh1 = (const float*)d_in[2];
    const float* bih1 = (const float*)d_in[3];
    const float* bhh1 = (const float*)d_in[4];
    const float* Wih2 = (const float*)d_in[5];
    const float* Whh2 = (const float*)d_in[6];
    const float* bih2 = (const float*)d_in[7];
    const float* bhh2 = (const float*)d_in[8];
    const float* Wih3 = (const float*)d_in[9];
    const float* Whh3 = (const float*)d_in[10];
    const float* bih3 = (const float*)d_in[11];
    const float* bhh3 = (const float*)d_in[12];
    const float* hW1  = (const float*)d_in[13];
    const float* hb1  = (const float*)d_in[14];
    const float* hW2  = (const float*)d_in[15];
    const float* hb2  = (const float*)d_in[16];
    const float* hW3  = (const float*)d_in[17];
    const float* hb3  = (const float*)d_in[18];
    float* out = (float*)d_out;

    float *y1, *xg2, *y2, *xg3, *s3;
    cudaGetSymbolAddress((void**)&y1,  g_y1);
    cudaGetSymbolAddress((void**)&xg2, g_xg2);
    cudaGetSymbolAddress((void**)&y2,  g_y2);
    cudaGetSymbolAddress((void**)&xg3, g_xg3);
    cudaGetSymbolAddress((void**)&s3,  g_sum3);

    static bool attr_set = false;
    if (!attr_set) {
        cudaFuncSetAttribute(lstm1_kernel,
            cudaFuncAttributeMaxDynamicSharedMemorySize, L1_SMEM);
        cudaFuncSetAttribute(lstm2_kernel,
            cudaFuncAttributeMaxDynamicSharedMemorySize, L2_SMEM_BYTES);
        attr_set = true;
    }

    const int M = BB * TT;
    lstm1_kernel<<<dim3(64, 2), 512, L1_SMEM>>>(x, Wih1, Whh1, bih1, bhh1, y1);
    gemm_bias_kernel<<<dim3(512 / 128, M / 128), 256>>>(y1, Wih2, bih2, bhh2, xg2, 512, 256);
    lstm2_kernel<<<512, 256, L2_SMEM_BYTES>>>(xg2, Whh2, y2);
    gemm_bias_kernel<<<dim3(128 / 128, M / 128), 256>>>(y2, Wih3, bih3, bhh3, xg3, 128, 128);
    lstm3_kernel<<<64, 256>>>(xg3, Whh3, s3);
    mlp_kernel<<<1, 256>>>(s3, hW1, hb1, hW2, hb2, hW3, hb3, out);
}

// round 10
// speedup vs baseline: 1.2130x; 1.1046x over previous
#include <cuda_runtime.h>
#include <cuda_bf16.h>
#include <math.h>

#define BB 256
#define TT 2048
typedef unsigned long long ull;
typedef unsigned int u32;

__device__ __nv_bfloat16 g_y1h[(size_t)BB * TT * 256];
__device__ __nv_bfloat16 g_y1l[(size_t)BB * TT * 256];
__device__ __nv_bfloat16 g_w2h[512 * 256];
__device__ __nv_bfloat16 g_w2l[512 * 256];
__device__ float g_xg2[(size_t)BB * TT * 512];
__device__ float g_y2 [(size_t)BB * TT * 128];
__device__ float g_xg3[(size_t)BB * TT * 128];
__device__ float g_sum3[BB * 32];

__device__ __forceinline__ float mysig(float v){ return __fdividef(1.0f, 1.0f + __expf(-v)); }
__device__ __forceinline__ float mytanh(float v){
    float e = __expf(2.0f * v);
    return 1.0f - 2.0f * __fdividef(1.0f, 1.0f + e);
}
__device__ __forceinline__ ull pk(float lo, float hi){
    ull r; asm("mov.b64 %0, {%1, %2};" : "=l"(r) : "f"(lo), "f"(hi)); return r;
}
__device__ __forceinline__ void upk(ull v, float& lo, float& hi){
    asm("mov.b64 {%0, %1}, %2;" : "=f"(lo), "=f"(hi) : "l"(v));
}
__device__ __forceinline__ void fma2(ull& d, ull a, ull b){
    asm("fma.rn.f32x2 %0, %1, %2, %0;" : "+l"(d) : "l"(a), "l"(b));
}
__device__ __forceinline__ void mma_bf16(float* d, const u32* a, const u32* b){
    asm volatile("mma.sync.aligned.m16n8k16.row.col.f32.bf16.bf16.f32 "
        "{%0,%1,%2,%3}, {%4,%5,%6,%7}, {%8,%9}, {%0,%1,%2,%3};"
        : "+f"(d[0]), "+f"(d[1]), "+f"(d[2]), "+f"(d[3])
        : "r"(a[0]), "r"(a[1]), "r"(a[2]), "r"(a[3]), "r"(b[0]), "r"(b[1]));
}

// ============ Layer 1: H=128, f32x2 k-pair SIMT (unchanged core) ============
#define L1_SWP  0
#define L1_H4   131072
#define L1_GAT  133120
#define L1_SMEM 141312

__global__ __launch_bounds__(512, 1) void lstm1_kernel(
    const float* __restrict__ x, const float* __restrict__ Wih,
    const float* __restrict__ Whh, const float* __restrict__ bih,
    const float* __restrict__ bhh,
    __nv_bfloat16* __restrict__ y1h, __nv_bfloat16* __restrict__ y1l)
{
    extern __shared__ char smraw[];
    ull*   sWp = (ull*)(smraw + L1_SWP);
    ull*   sh4 = (ull*)(smraw + L1_H4);
    float* sg  = (float*)(smraw + L1_GAT);
    float* sh4f = (float*)sh4;

    const int dir = blockIdx.y, bg0 = blockIdx.x * 4;
    const int r = threadIdx.x;
    const float* WD = Whh + (size_t)dir * 512 * 128;

    ull Wreg[32];
    #pragma unroll
    for (int kp = 0; kp < 32; kp++)
        Wreg[kp] = pk(WD[r * 128 + 2 * kp], WD[r * 128 + 2 * kp + 1]);
    for (int kp = 0; kp < 32; kp++)
        sWp[kp * 512 + r] = pk(WD[r * 128 + 64 + 2 * kp], WD[r * 128 + 65 + 2 * kp]);

    const float wx0  = Wih[dir * 1024 + r * 2];
    const float wx1  = Wih[dir * 1024 + r * 2 + 1];
    const float bias = bih[dir * 512 + r] + bhh[dir * 512 + r];
    const int gate = r >> 7;
    const int cb = r >> 7, j = r & 127;
    float cc = 0.0f;

    if (r < 256) sh4[r] = 0ull;
    __syncthreads();

    for (int s = 0; s < TT; s++) {
        const int t = dir ? (TT - 1 - s) : s;
        float2 xv0 = __ldg((const float2*)(x + ((size_t)(bg0 + 0) * TT + t) * 2));
        float2 xv1 = __ldg((const float2*)(x + ((size_t)(bg0 + 1) * TT + t) * 2));
        float2 xv2 = __ldg((const float2*)(x + ((size_t)(bg0 + 2) * TT + t) * 2));
        float2 xv3 = __ldg((const float2*)(x + ((size_t)(bg0 + 3) * TT + t) * 2));

        ull a0 = 0ull, a1 = 0ull, a2 = 0ull, a3 = 0ull;
        #pragma unroll
        for (int kp = 0; kp < 32; kp++) {
            ulonglong2 p0 = *(const ulonglong2*)(sh4 + kp * 4);
            ulonglong2 p1 = *(const ulonglong2*)(sh4 + kp * 4 + 2);
            fma2(a0, Wreg[kp], p0.x);
            fma2(a1, Wreg[kp], p0.y);
            fma2(a2, Wreg[kp], p1.x);
            fma2(a3, Wreg[kp], p1.y);
        }
        #pragma unroll
        for (int kp = 0; kp < 32; kp++) {
            ull w = sWp[kp * 512 + r];
            ulonglong2 p0 = *(const ulonglong2*)(sh4 + (kp + 32) * 4);
            ulonglong2 p1 = *(const ulonglong2*)(sh4 + (kp + 32) * 4 + 2);
            fma2(a0, w, p0.x);
            fma2(a1, w, p0.y);
            fma2(a2, w, p1.x);
            fma2(a3, w, p1.y);
        }

        float l0, h0, l1, h1, l2, h2, l3, h3;
        upk(a0, l0, h0); upk(a1, l1, h1); upk(a2, l2, h2); upk(a3, l3, h3);
        float v0 = fmaf(wx0, xv0.x, fmaf(wx1, xv0.y, bias + l0 + h0));
        float v1 = fmaf(wx0, xv1.x, fmaf(wx1, xv1.y, bias + l1 + h1));
        float v2 = fmaf(wx0, xv2.x, fmaf(wx1, xv2.y, bias + l2 + h2));
        float v3 = fmaf(wx0, xv3.x, fmaf(wx1, xv3.y, bias + l3 + h3));
        if (gate == 2) {
            sg[0*512 + r] = mytanh(v0); sg[1*512 + r] = mytanh(v1);
            sg[2*512 + r] = mytanh(v2); sg[3*512 + r] = mytanh(v3);
        } else {
            sg[0*512 + r] = mysig(v0); sg[1*512 + r] = mysig(v1);
            sg[2*512 + r] = mysig(v2); sg[3*512 + r] = mysig(v3);
        }
        __syncthreads();

        {
            float i_ = sg[cb*512 + j];
            float f_ = sg[cb*512 + j + 128];
            float gg = sg[cb*512 + j + 256];
            float o_ = sg[cb*512 + j + 384];
            cc = fmaf(f_, cc, i_ * gg);
            float h = o_ * mytanh(cc);
            size_t oi = ((size_t)(bg0 + cb) * TT + t) * 256 + dir * 128 + j;
            __nv_bfloat16 hh = __float2bfloat16(h);
            y1h[oi] = hh;
            y1l[oi] = __float2bfloat16(h - __bfloat162float(hh));
            sh4f[(j >> 1) * 8 + cb * 2 + (j & 1)] = h;
        }
        __syncthreads();
    }
}

// ============ weight split prep ============
__global__ void wsplit_kernel(const float* __restrict__ W,
    __nv_bfloat16* __restrict__ wh, __nv_bfloat16* __restrict__ wl, int n)
{
    int i = blockIdx.x * 256 + threadIdx.x;
    if (i < n) {
        float v = W[i];
        __nv_bfloat16 h = __float2bfloat16(v);
        wh[i] = h;
        wl[i] = __float2bfloat16(v - __bfloat162float(h));
    }
}

// ============ gemm1 via mma.sync bf16 3-term split ============
// C[M,512] = Ah*Bh + Al*Bh + Ah*Bl + bias. BM=BN=128, BK=32, 8 warps (4m x 2n).
#define GPAD 40
__global__ __launch_bounds__(256) void gemm1_hmma(
    const __nv_bfloat16* __restrict__ Ah, const __nv_bfloat16* __restrict__ Al,
    const __nv_bfloat16* __restrict__ Bh, const __nv_bfloat16* __restrict__ Bl,
    const float* __restrict__ b1, const float* __restrict__ b2,
    float* __restrict__ C)
{
    __shared__ __nv_bfloat16 sAh[128][GPAD], sAl[128][GPAD];
    __shared__ __nv_bfloat16 sBh[128][GPAD], sBl[128][GPAD];
    const int m0 = blockIdx.y * 128, n0 = blockIdx.x * 128;
    const int tid = threadIdx.x, wid = tid >> 5, lane = tid & 31;
    const int wm = wid & 3, wn = wid >> 2;
    const int g = lane >> 2, tq = lane & 3;

    float D[2][8][4];
    #pragma unroll
    for (int mt = 0; mt < 2; mt++)
        #pragma unroll
        for (int nt = 0; nt < 8; nt++)
            #pragma unroll
            for (int q = 0; q < 4; q++) D[mt][nt][q] = 0.0f;

    for (int kb = 0; kb < 256; kb += 32) {
        #pragma unroll
        for (int i = 0; i < 2; i++) {
            int c = tid * 2 + i;            // 0..511
            int row = c >> 2, q = c & 3;
            *(uint4*)&sAh[row][q * 8] = *(const uint4*)(Ah + (size_t)(m0 + row) * 256 + kb + q * 8);
            *(uint4*)&sAl[row][q * 8] = *(const uint4*)(Al + (size_t)(m0 + row) * 256 + kb + q * 8);
            *(uint4*)&sBh[row][q * 8] = *(const uint4*)(Bh + (size_t)(n0 + row) * 256 + kb + q * 8);
            *(uint4*)&sBl[row][q * 8] = *(const uint4*)(Bl + (size_t)(n0 + row) * 256 + kb + q * 8);
        }
        __syncthreads();
        #pragma unroll
        for (int kk = 0; kk < 2; kk++) {
            u32 ah[2][4], al[2][4], bh[8][2], bl[8][2];
            #pragma unroll
            for (int mt = 0; mt < 2; mt++) {
                int r0 = wm * 32 + mt * 16 + g;
                int kc = kk * 16 + 2 * tq;
                ah[mt][0] = *(const u32*)&sAh[r0][kc];
                ah[mt][1] = *(const u32*)&sAh[r0 + 8][kc];
                ah[mt][2] = *(const u32*)&sAh[r0][kc + 8];
                ah[mt][3] = *(const u32*)&sAh[r0 + 8][kc + 8];
                al[mt][0] = *(const u32*)&sAl[r0][kc];
                al[mt][1] = *(const u32*)&sAl[r0 + 8][kc];
                al[mt][2] = *(const u32*)&sAl[r0][kc + 8];
                al[mt][3] = *(const u32*)&sAl[r0 + 8][kc + 8];
            }
            #pragma unroll
            for (int nt = 0; nt < 8; nt++) {
                int n_ = wn * 64 + nt * 8 + g;
                int kc = kk * 16 + 2 * tq;
                bh[nt][0] = *(const u32*)&sBh[n_][kc];
                bh[nt][1] = *(const u32*)&sBh[n_][kc + 8];
                bl[nt][0] = *(const u32*)&sBl[n_][kc];
                bl[nt][1] = *(const u32*)&sBl[n_][kc + 8];
            }
            #pragma unroll
            for (int mt = 0; mt < 2; mt++)
                #pragma unroll
                for (int nt = 0; nt < 8; nt++) {
                    mma_bf16(D[mt][nt], ah[mt], bh[nt]);
                    mma_bf16(D[mt][nt], al[mt], bh[nt]);
                    mma_bf16(D[mt][nt], ah[mt], bl[nt]);
                }
        }
        __syncthreads();
    }
    #pragma unroll
    for (int mt = 0; mt < 2; mt++) {
        size_t r0 = (size_t)(m0 + wm * 32 + mt * 16 + g);
        size_t r1 = r0 + 8;
        #pragma unroll
        for (int nt = 0; nt < 8; nt++) {
            int c0 = n0 + wn * 64 + nt * 8 + 2 * tq;
            float bA = b1[c0] + b2[c0];
            float bB = b1[c0 + 1] + b2[c0 + 1];
            C[r0 * 512 + c0]     = D[mt][nt][0] + bA;
            C[r0 * 512 + c0 + 1] = D[mt][nt][1] + bB;
            C[r1 * 512 + c0]     = D[mt][nt][2] + bA;
            C[r1 * 512 + c0 + 1] = D[mt][nt][3] + bB;
        }
    }
}

// ============ fp32 GEMM + bias (gemm2): BM=BN=128, BK=16, 8x8 ============
__global__ __launch_bounds__(256) void gemm_bias_kernel(
    const float* __restrict__ A, const float* __restrict__ B,
    const float* __restrict__ b1, const float* __restrict__ b2,
    float* __restrict__ C, int N, int K)
{
    __shared__ float As[16][128];
    __shared__ float Bs[16][128];
    const int m0 = blockIdx.y * 128, n0 = blockIdx.x * 128;
    const int tid = threadIdx.x;
    const int tx = tid & 15, ty = tid >> 4;

    float acc[8][8];
    #pragma unroll
    for (int i = 0; i < 8; i++)
        #pragma unroll
        for (int jj = 0; jj < 8; jj++) acc[i][jj] = 0.0f;

    for (int k0 = 0; k0 < K; k0 += 16) {
        #pragma unroll
        for (int i = 0; i < 2; i++) {
            int id = tid * 2 + i;
            int row = id >> 2, c4 = (id & 3) * 4;
            float4 v = *(const float4*)&A[(size_t)(m0 + row) * K + k0 + c4];
            As[c4+0][row] = v.x; As[c4+1][row] = v.y; As[c4+2][row] = v.z; As[c4+3][row] = v.w;
            float4 w = *(const float4*)&B[(size_t)(n0 + row) * K + k0 + c4];
            Bs[c4+0][row] = w.x; Bs[c4+1][row] = w.y; Bs[c4+2][row] = w.z; Bs[c4+3][row] = w.w;
        }
        __syncthreads();
        #pragma unroll
        for (int k = 0; k < 16; k++) {
            float ar[8], br[8];
            *(float4*)(ar)   = *(const float4*)&As[k][ty * 8];
            *(float4*)(ar+4) = *(const float4*)&As[k][ty * 8 + 4];
            *(float4*)(br)   = *(const float4*)&Bs[k][tx * 8];
            *(float4*)(br+4) = *(const float4*)&Bs[k][tx * 8 + 4];
            #pragma unroll
            for (int i = 0; i < 8; i++)
                #pragma unroll
                for (int jj = 0; jj < 8; jj++)
                    acc[i][jj] = fmaf(ar[i], br[jj], acc[i][jj]);
        }
        __syncthreads();
    }
    float bb[8];
    #pragma unroll
    for (int jj = 0; jj < 8; jj++) { int c = n0 + tx * 8 + jj; bb[jj] = b1[c] + b2[c]; }
    #pragma unroll
    for (int i = 0; i < 8; i++) {
        size_t row = (size_t)(m0 + ty * 8 + i);
        float4 o0 = {acc[i][0]+bb[0], acc[i][1]+bb[1], acc[i][2]+bb[2], acc[i][3]+bb[3]};
        float4 o1 = {acc[i][4]+bb[4], acc[i][5]+bb[5], acc[i][6]+bb[6], acc[i][7]+bb[7]};
        *(float4*)&C[row * N + n0 + tx * 8]     = o0;
        *(float4*)&C[row * N + n0 + tx * 8 + 4] = o1;
    }
}

// ============ Layer 2: H=64, CTA per chain ============
#define L2_SMEM_BYTES (32 * 256 * 8 + 64 * 4 + 256 * 4)
__global__ __launch_bounds__(256, 1) void lstm2_kernel(
    const float* __restrict__ xg, const float* __restrict__ Whh,
    float* __restrict__ y2)
{
    extern __shared__ char smraw[];
    ull*   sW2 = (ull*)smraw;
    float* sh  = (float*)(smraw + 32 * 256 * 8);
    float* sg  = sh + 64;
    const int r = threadIdx.x;
    const int b = blockIdx.x >> 1, dir = blockIdx.x & 1;
    const int gate = r >> 6, j = r & 63;
    const float* WhhD = Whh + (size_t)dir * 256 * 64;

    for (int i = r; i < 32 * 256; i += 256) {
        int kp = i >> 8, rr = i & 255;
        sW2[i] = *(const ull*)(WhhD + rr * 64 + 2 * kp);
    }
    if (r < 64) sh[r] = 0.0f;
    float cc = 0.0f;
    __syncthreads();

    const float* xgb = xg + (size_t)b * TT * 512 + dir * 256 + r;
    const int t0 = dir ? (TT - 1) : 0;
    float xt = __ldg(xgb + (size_t)t0 * 512);

    for (int s = 0; s < TT; s++) {
        const int t = dir ? (TT - 1 - s) : s;
        float xnext = 0.0f;
        if (s + 1 < TT) {
            const int tn = dir ? (TT - 2 - s) : (s + 1);
            xnext = __ldg(xgb + (size_t)tn * 512);
        }
        ull accA = 0ull, accB = 0ull;
        #pragma unroll
        for (int kp = 0; kp < 32; kp += 2) {
            fma2(accA, sW2[kp * 256 + r],       *(const ull*)(sh + 2 * kp));
            fma2(accB, sW2[(kp + 1) * 256 + r], *(const ull*)(sh + 2 * kp + 2));
        }
        float alo, ahi, blo, bhi;
        upk(accA, alo, ahi); upk(accB, blo, bhi);
        float v = xt + (alo + ahi) + (blo + bhi);
        sg[r] = (gate == 2) ? mytanh(v) : mysig(v);
        __syncthreads();
        if (r < 64) {
            float i_ = sg[j], f_ = sg[j+64], gg = sg[j+128], o_ = sg[j+192];
            cc = fmaf(f_, cc, i_ * gg);
            float h = o_ * mytanh(cc);
            sh[j] = h;
            y2[((size_t)b * TT + t) * 128 + dir * 64 + j] = h;
        }
        __syncthreads();
        xt = xnext;
    }
}

// ============ Layer 3 + mean: warp per chain ============
__global__ __launch_bounds__(256, 1) void lstm3_kernel(
    const float* __restrict__ xg, const float* __restrict__ Whh,
    float* __restrict__ s3)
{
    __shared__ float shh[8][16];
    const int tid = threadIdx.x, wid = tid >> 5, lane = tid & 31;
    const int pg = blockIdx.x * 8 + wid;
    const int b = pg >> 1, dir = pg & 1;
    const int r0 = lane, r1 = lane + 32;
    const float* WhhD = Whh + (size_t)dir * 64 * 16;
    float* shp = shh[wid];

    ull w0[8], w1[8];
    #pragma unroll
    for (int kp = 0; kp < 8; kp++) {
        w0[kp] = *(const ull*)(WhhD + r0 * 16 + 2 * kp);
        w1[kp] = *(const ull*)(WhhD + r1 * 16 + 2 * kp);
    }
    if (lane < 16) shp[lane] = 0.0f;
    float cc = 0.0f, sum = 0.0f;
    __syncwarp();

    const float* xgb = xg + (size_t)b * TT * 128 + dir * 64;
    const int t0 = dir ? (TT - 1) : 0;
    float xt0 = __ldg(xgb + (size_t)t0 * 128 + r0);
    float xt1 = __ldg(xgb + (size_t)t0 * 128 + r1);

    for (int s = 0; s < TT; s++) {
        float xn0 = 0.0f, xn1 = 0.0f;
        if (s + 1 < TT) {
            const int tn = dir ? (TT - 2 - s) : (s + 1);
            xn0 = __ldg(xgb + (size_t)tn * 128 + r0);
            xn1 = __ldg(xgb + (size_t)tn * 128 + r1);
        }
        ull a0 = 0ull, a1 = 0ull;
        #pragma unroll
        for (int kp = 0; kp < 8; kp++) {
            ull hb = *(const ull*)(shp + 2 * kp);
            fma2(a0, w0[kp], hb);
            fma2(a1, w1[kp], hb);
        }
        float l0, h0, l1, h1;
        upk(a0, l0, h0); upk(a1, l1, h1);
        float v0 = xt0 + l0 + h0, v1 = xt1 + l1 + h1;
        float g0 = mysig(v0);
        float g1 = (lane < 16) ? mytanh(v1) : mysig(v1);
        float f_ = __shfl_down_sync(0xffffffffu, g0, 16);
        float o_ = __shfl_down_sync(0xffffffffu, g1, 16);
        if (lane < 16) {
            cc = fmaf(f_, cc, g0 * g1);
            float h = o_ * mytanh(cc);
            shp[lane] = h;
            sum += h;
        }
        __syncwarp();
        xt0 = xn0; xt1 = xn1;
    }
    if (lane < 16) s3[b * 32 + dir * 16 + lane] = sum * (1.0f / TT);
}

// ============ MLP head ============
__global__ void mlp_kernel(
    const float* __restrict__ s3,
    const float* __restrict__ hW1, const float* __restrict__ hb1,
    const float* __restrict__ hW2, const float* __restrict__ hb2,
    const float* __restrict__ hW3, const float* __restrict__ hb3,
    float* __restrict__ out)
{
    int b = blockIdx.x * blockDim.x + threadIdx.x;
    if (b >= BB) return;
    float s[32];
    #pragma unroll
    for (int k = 0; k < 32; k++) s[k] = s3[b * 32 + k];
    float h1[64];
    for (int o = 0; o < 64; o++) {
        float a = hb1[o];
        #pragma unroll
        for (int k = 0; k < 32; k++) a = fmaf(s[k], hW1[o * 32 + k], a);
        h1[o] = fmaxf(a, 0.0f);
    }
    float h2[16];
    for (int o = 0; o < 16; o++) {
        float a = hb2[o];
        #pragma unroll
        for (int k = 0; k < 64; k++) a = fmaf(h1[k], hW2[o * 64 + k], a);
        h2[o] = fmaxf(a, 0.0f);
    }
    for (int o = 0; o < 20; o++) {
        float a = hb3[o];
        #pragma unroll
        for (int k = 0; k < 16; k++) a = fmaf(h2[k], hW3[o * 16 + k], a);
        out[b * 20 + o] = a;
    }
}

extern "C" void kernel_launch(void* const* d_in, const int* in_sizes, int n_in,
                              void* d_out, int out_size)
{
    const float* x    = (const float*)d_in[0];
    const float* Wih1 = (const float*)d_in[1];
    const float* Whh1 = (const float*)d_in[2];
    const float* bih1 = (const float*)d_in[3];
    const float* bhh1 = (const float*)d_in[4];
    const float* Wih2 = (const float*)d_in[5];
    const float* Whh2 = (const float*)d_in[6];
    const float* bih2 = (const float*)d_in[7];
    const float* bhh2 = (const float*)d_in[8];
    const float* Wih3 = (const float*)d_in[9];
    const float* Whh3 = (const float*)d_in[10];
    const float* bih3 = (const float*)d_in[11];
    const float* bhh3 = (const float*)d_in[12];
    const float* hW1  = (const float*)d_in[13];
    const float* hb1  = (const float*)d_in[14];
    const float* hW2  = (const float*)d_in[15];
    const float* hb2  = (const float*)d_in[16];
    const float* hW3  = (const float*)d_in[17];
    const float* hb3  = (const float*)d_in[18];
    float* out = (float*)d_out;

    __nv_bfloat16 *y1h, *y1l, *w2h, *w2l;
    float *xg2, *y2, *xg3, *s3;
    cudaGetSymbolAddress((void**)&y1h, g_y1h);
    cudaGetSymbolAddress((void**)&y1l, g_y1l);
    cudaGetSymbolAddress((void**)&w2h, g_w2h);
    cudaGetSymbolAddress((void**)&w2l, g_w2l);
    cudaGetSymbolAddress((void**)&xg2, g_xg2);
    cudaGetSymbolAddress((void**)&y2,  g_y2);
    cudaGetSymbolAddress((void**)&xg3, g_xg3);
    cudaGetSymbolAddress((void**)&s3,  g_sum3);

    static bool attr_set = false;
    if (!attr_set) {
        cudaFuncSetAttribute(lstm1_kernel,
            cudaFuncAttributeMaxDynamicSharedMemorySize, L1_SMEM);
        cudaFuncSetAttribute(lstm2_kernel,
            cudaFuncAttributeMaxDynamicSharedMemorySize, L2_SMEM_BYTES);
        attr_set = true;
    }

    const int M = BB * TT;
    wsplit_kernel<<<512, 256>>>(Wih2, w2h, w2l, 512 * 256);
    lstm1_kernel<<<dim3(64, 2), 512, L1_SMEM>>>(x, Wih1, Whh1, bih1, bhh1, y1h, y1l);
    gemm1_hmma<<<dim3(4, M / 128), 256>>>(y1h, y1l, w2h, w2l, bih2, bhh2, xg2);
    lstm2_kernel<<<512, 256, L2_SMEM_BYTES>>>(xg2, Whh2, y2);
    gemm_bias_kernel<<<dim3(1, M / 128), 256>>>(y2, Wih3, bih3, bhh3, xg3, 128, 128);
    lstm3_kernel<<<64, 256>>>(xg3, Whh3, s3);
    mlp_kernel<<<1, 256>>>(s3, hW1, hb1, hW2, hb2, hW3, hb3, out);
}

// round 11
// speedup vs baseline: 1.6482x; 1.3588x over previous
#include <cuda_runtime.h>
#include <cuda_bf16.h>
#include <math.h>

#define BB 256
#define TT 2048
typedef unsigned long long ull;
typedef unsigned int u32;

__device__ __nv_bfloat16 g_y1h[(size_t)BB * TT * 256];
__device__ __nv_bfloat16 g_y1l[(size_t)BB * TT * 256];
__device__ __nv_bfloat16 g_w2h[512 * 256];
__device__ __nv_bfloat16 g_w2l[512 * 256];
__device__ float g_xg2[(size_t)BB * TT * 512];
__device__ float g_y2 [(size_t)BB * TT * 128];
__device__ float g_xg3[(size_t)BB * TT * 128];
__device__ float g_sum3[BB * 32];

__device__ __forceinline__ float mysig(float v){ return __fdividef(1.0f, 1.0f + __expf(-v)); }
__device__ __forceinline__ float mytanh(float v){
    float e = __expf(2.0f * v);
    return 1.0f - 2.0f * __fdividef(1.0f, 1.0f + e);
}
__device__ __forceinline__ ull pk(float lo, float hi){
    ull r; asm("mov.b64 %0, {%1, %2};" : "=l"(r) : "f"(lo), "f"(hi)); return r;
}
__device__ __forceinline__ void upk(ull v, float& lo, float& hi){
    asm("mov.b64 {%0, %1}, %2;" : "=f"(lo), "=f"(hi) : "l"(v));
}
__device__ __forceinline__ void fma2(ull& d, ull a, ull b){
    asm("fma.rn.f32x2 %0, %1, %2, %0;" : "+l"(d) : "l"(a), "l"(b));
}
__device__ __forceinline__ void mma_bf16(float* d, const u32* a, const u32* b){
    asm volatile("mma.sync.aligned.m16n8k16.row.col.f32.bf16.bf16.f32 "
        "{%0,%1,%2,%3}, {%4,%5,%6,%7}, {%8,%9}, {%0,%1,%2,%3};"
        : "+f"(d[0]), "+f"(d[1]), "+f"(d[2]), "+f"(d[3])
        : "r"(a[0]), "r"(a[1]), "r"(a[2]), "r"(a[3]), "r"(b[0]), "r"(b[1]));
}
__device__ __forceinline__ u32 hi2(float a, float b){
    return (u32)__bfloat16_as_ushort(__float2bfloat16(a))
         | ((u32)__bfloat16_as_ushort(__float2bfloat16(b)) << 16);
}
__device__ __forceinline__ u32 lo2(float a, float b){
    float ra = a - __bfloat162float(__float2bfloat16(a));
    float rb = b - __bfloat162float(__float2bfloat16(b));
    return hi2(ra, rb);
}

// ============ Layer 1 via mma.sync: CTA = 4 batches x 1 dir, grid (64,2) ====
// 16 warps, warp w owns m-tiles {2w,2w+1} (rows 32w..32w+31). A_hi in regs,
// A_lo in smem fragment-linear, h (B) in smem fragment-permuted hi/lo planes.
#define L1_ALO  0          // u32[16][2][8][32][4] = 128KB
#define L1_BHI  131072     // u32[8][32][2] = 2KB  (word0=b0, word1=b1)
#define L1_BLO  133120     // 2KB
#define L1_GAT  135168     // float[512][4] = 8KB
#define L1_SMEM 143360

__global__ __launch_bounds__(512, 1) void lstm1_mma(
    const float* __restrict__ x, const float* __restrict__ Wih,
    const float* __restrict__ Whh, const float* __restrict__ bih,
    const float* __restrict__ bhh,
    __nv_bfloat16* __restrict__ y1h, __nv_bfloat16* __restrict__ y1l)
{
    extern __shared__ char sm[];
    u32*   sALo = (u32*)(sm + L1_ALO);
    float* sgat = (float*)(sm + L1_GAT);

    const int tid = threadIdx.x, w = tid >> 5, l = tid & 31;
    const int g = l >> 2, tq = l & 3;
    const int dir = blockIdx.y, bg0 = blockIdx.x * 4;
    const float* WD = Whh + (size_t)dir * 512 * 128;

    // A fragments: hi in regs, lo to smem
    u32 Ah[2][8][4];
    #pragma unroll
    for (int mt = 0; mt < 2; mt++)
        #pragma unroll
        for (int ks = 0; ks < 8; ks++) {
            int R = 32 * w + 16 * mt + g, C = 16 * ks + 2 * tq;
            const float* p0 = WD + (size_t)R * 128 + C;
            const float* p1 = WD + (size_t)(R + 8) * 128 + C;
            Ah[mt][ks][0] = hi2(p0[0], p0[1]);
            Ah[mt][ks][1] = hi2(p1[0], p1[1]);
            Ah[mt][ks][2] = hi2(p0[8], p0[9]);
            Ah[mt][ks][3] = hi2(p1[8], p1[9]);
            u32* q = sALo + (((w * 2 + mt) * 8 + ks) * 32 + l) * 4;
            q[0] = lo2(p0[0], p0[1]);
            q[1] = lo2(p1[0], p1[1]);
            q[2] = lo2(p0[8], p0[9]);
            q[3] = lo2(p1[8], p1[9]);
        }
    // zero B planes
    for (int i = tid; i < 1024; i += 512) ((u32*)(sm + L1_BHI))[i] = 0;

    // combine-role constants: thread = (batch cb, unit j)
    const int cb = tid >> 7, j = tid & 127;
    float bias4[4], wx04[4], wx14[4];
    #pragma unroll
    for (int q = 0; q < 4; q++) {
        int rq = j + 128 * q;
        bias4[q] = bih[dir * 512 + rq] + bhh[dir * 512 + rq];
        wx04[q] = Wih[dir * 1024 + rq * 2];
        wx14[q] = Wih[dir * 1024 + rq * 2 + 1];
    }
    // B-perm write offset for (k=j, n=cb)
    const u32 bko = (u32)(j >> 4) * 256 + (u32)(4 * cb + ((j & 7) >> 1)) * 8
                  + (u32)((j >> 3) & 1) * 4 + (u32)(j & 1) * 2;
    float cc = 0.0f;
    __syncthreads();

    for (int s = 0; s < TT; s++) {
        const int t = dir ? (TT - 1 - s) : s;

        float D0[4] = {0.f, 0.f, 0.f, 0.f};
        float D1[4] = {0.f, 0.f, 0.f, 0.f};
        #pragma unroll
        for (int ks = 0; ks < 8; ks++) {
            uint2 bh = *(const uint2*)(sm + L1_BHI + ks * 256 + l * 8);
            uint2 bl = *(const uint2*)(sm + L1_BLO + ks * 256 + l * 8);
            uint4 al0 = *(const uint4*)(sALo + (((w * 2 + 0) * 8 + ks) * 32 + l) * 4);
            uint4 al1 = *(const uint4*)(sALo + (((w * 2 + 1) * 8 + ks) * 32 + l) * 4);
            mma_bf16(D0, Ah[0][ks], &bh.x);
            mma_bf16(D0, (const u32*)&al0, &bh.x);
            mma_bf16(D0, Ah[0][ks], &bl.x);
            mma_bf16(D1, Ah[1][ks], &bh.x);
            mma_bf16(D1, (const u32*)&al1, &bh.x);
            mma_bf16(D1, Ah[1][ks], &bl.x);
        }
        if (tq < 2) {
            int r0 = 32 * w + g;
            *(float2*)(sm + L1_GAT + r0 * 16 + tq * 8)        = make_float2(D0[0], D0[1]);
            *(float2*)(sm + L1_GAT + (r0 + 8) * 16 + tq * 8)  = make_float2(D0[2], D0[3]);
            *(float2*)(sm + L1_GAT + (r0 + 16) * 16 + tq * 8) = make_float2(D1[0], D1[1]);
            *(float2*)(sm + L1_GAT + (r0 + 24) * 16 + tq * 8) = make_float2(D1[2], D1[3]);
        }
        __syncthreads();

        {
            float2 xv = __ldg((const float2*)(x + ((size_t)(bg0 + cb) * TT + t) * 2));
            float vi = sgat[j * 4 + cb]          + bias4[0] + wx04[0] * xv.x + wx14[0] * xv.y;
            float vf = sgat[(j + 128) * 4 + cb]  + bias4[1] + wx04[1] * xv.x + wx14[1] * xv.y;
            float vg = sgat[(j + 256) * 4 + cb]  + bias4[2] + wx04[2] * xv.x + wx14[2] * xv.y;
            float vo = sgat[(j + 384) * 4 + cb]  + bias4[3] + wx04[3] * xv.x + wx14[3] * xv.y;
            float i_ = mysig(vi), f_ = mysig(vf), gg = mytanh(vg), o_ = mysig(vo);
            cc = fmaf(f_, cc, i_ * gg);
            float h = o_ * mytanh(cc);
            size_t oi = ((size_t)(bg0 + cb) * TT + t) * 256 + dir * 128 + j;
            __nv_bfloat16 hh = __float2bfloat16(h);
            __nv_bfloat16 ll = __float2bfloat16(h - __bfloat162float(hh));
            y1h[oi] = hh;
            y1l[oi] = ll;
            *(__nv_bfloat16*)(sm + L1_BHI + bko) = hh;
            *(__nv_bfloat16*)(sm + L1_BLO + bko) = ll;
        }
        __syncthreads();
    }
}

// ============ weight split prep ============
__global__ void wsplit_kernel(const float* __restrict__ W,
    __nv_bfloat16* __restrict__ wh, __nv_bfloat16* __restrict__ wl, int n)
{
    int i = blockIdx.x * 256 + threadIdx.x;
    if (i < n) {
        float v = W[i];
        __nv_bfloat16 h = __float2bfloat16(v);
        wh[i] = h;
        wl[i] = __float2bfloat16(v - __bfloat162float(h));
    }
}

// ============ gemm1 via mma.sync bf16 3-term split (unchanged) ============
#define GPAD 40
__global__ __launch_bounds__(256) void gemm1_hmma(
    const __nv_bfloat16* __restrict__ Ah, const __nv_bfloat16* __restrict__ Al,
    const __nv_bfloat16* __restrict__ Bh, const __nv_bfloat16* __restrict__ Bl,
    const float* __restrict__ b1, const float* __restrict__ b2,
    float* __restrict__ C)
{
    __shared__ __nv_bfloat16 sAh[128][GPAD], sAl[128][GPAD];
    __shared__ __nv_bfloat16 sBh[128][GPAD], sBl[128][GPAD];
    const int m0 = blockIdx.y * 128, n0 = blockIdx.x * 128;
    const int tid = threadIdx.x, wid = tid >> 5, lane = tid & 31;
    const int wm = wid & 3, wn = wid >> 2;
    const int g = lane >> 2, tq = lane & 3;

    float D[2][8][4];
    #pragma unroll
    for (int mt = 0; mt < 2; mt++)
        #pragma unroll
        for (int nt = 0; nt < 8; nt++)
            #pragma unroll
            for (int q = 0; q < 4; q++) D[mt][nt][q] = 0.0f;

    for (int kb = 0; kb < 256; kb += 32) {
        #pragma unroll
        for (int i = 0; i < 2; i++) {
            int c = tid * 2 + i;
            int row = c >> 2, q = c & 3;
            *(uint4*)&sAh[row][q * 8] = *(const uint4*)(Ah + (size_t)(m0 + row) * 256 + kb + q * 8);
            *(uint4*)&sAl[row][q * 8] = *(const uint4*)(Al + (size_t)(m0 + row) * 256 + kb + q * 8);
            *(uint4*)&sBh[row][q * 8] = *(const uint4*)(Bh + (size_t)(n0 + row) * 256 + kb + q * 8);
            *(uint4*)&sBl[row][q * 8] = *(const uint4*)(Bl + (size_t)(n0 + row) * 256 + kb + q * 8);
        }
        __syncthreads();
        #pragma unroll
        for (int kk = 0; kk < 2; kk++) {
            u32 ah[2][4], al[2][4], bh[8][2], bl[8][2];
            #pragma unroll
            for (int mt = 0; mt < 2; mt++) {
                int r0 = wm * 32 + mt * 16 + g;
                int kc = kk * 16 + 2 * tq;
                ah[mt][0] = *(const u32*)&sAh[r0][kc];
                ah[mt][1] = *(const u32*)&sAh[r0 + 8][kc];
                ah[mt][2] = *(const u32*)&sAh[r0][kc + 8];
                ah[mt][3] = *(const u32*)&sAh[r0 + 8][kc + 8];
                al[mt][0] = *(const u32*)&sAl[r0][kc];
                al[mt][1] = *(const u32*)&sAl[r0 + 8][kc];
                al[mt][2] = *(const u32*)&sAl[r0][kc + 8];
                al[mt][3] = *(const u32*)&sAl[r0 + 8][kc + 8];
            }
            #pragma unroll
            for (int nt = 0; nt < 8; nt++) {
                int n_ = wn * 64 + nt * 8 + g;
                int kc = kk * 16 + 2 * tq;
                bh[nt][0] = *(const u32*)&sBh[n_][kc];
                bh[nt][1] = *(const u32*)&sBh[n_][kc + 8];
                bl[nt][0] = *(const u32*)&sBl[n_][kc];
                bl[nt][1] = *(const u32*)&sBl[n_][kc + 8];
            }
            #pragma unroll
            for (int mt = 0; mt < 2; mt++)
                #pragma unroll
                for (int nt = 0; nt < 8; nt++) {
                    mma_bf16(D[mt][nt], ah[mt], bh[nt]);
                    mma_bf16(D[mt][nt], al[mt], bh[nt]);
                    mma_bf16(D[mt][nt], ah[mt], bl[nt]);
                }
        }
        __syncthreads();
    }
    #pragma unroll
    for (int mt = 0; mt < 2; mt++) {
        size_t r0 = (size_t)(m0 + wm * 32 + mt * 16 + g);
        size_t r1 = r0 + 8;
        #pragma unroll
        for (int nt = 0; nt < 8; nt++) {
            int c0 = n0 + wn * 64 + nt * 8 + 2 * tq;
            float bA = b1[c0] + b2[c0];
            float bB = b1[c0 + 1] + b2[c0 + 1];
            C[r0 * 512 + c0]     = D[mt][nt][0] + bA;
            C[r0 * 512 + c0 + 1] = D[mt][nt][1] + bB;
            C[r1 * 512 + c0]     = D[mt][nt][2] + bA;
            C[r1 * 512 + c0 + 1] = D[mt][nt][3] + bB;
        }
    }
}

// ============ fp32 GEMM + bias (gemm2) ============
__global__ __launch_bounds__(256) void gemm_bias_kernel(
    const float* __restrict__ A, const float* __restrict__ B,
    const float* __restrict__ b1, const float* __restrict__ b2,
    float* __restrict__ C, int N, int K)
{
    __shared__ float As[16][128];
    __shared__ float Bs[16][128];
    const int m0 = blockIdx.y * 128, n0 = blockIdx.x * 128;
    const int tid = threadIdx.x;
    const int tx = tid & 15, ty = tid >> 4;

    float acc[8][8];
    #pragma unroll
    for (int i = 0; i < 8; i++)
        #pragma unroll
        for (int jj = 0; jj < 8; jj++) acc[i][jj] = 0.0f;

    for (int k0 = 0; k0 < K; k0 += 16) {
        #pragma unroll
        for (int i = 0; i < 2; i++) {
            int id = tid * 2 + i;
            int row = id >> 2, c4 = (id & 3) * 4;
            float4 v = *(const float4*)&A[(size_t)(m0 + row) * K + k0 + c4];
            As[c4+0][row] = v.x; As[c4+1][row] = v.y; As[c4+2][row] = v.z; As[c4+3][row] = v.w;
            float4 w = *(const float4*)&B[(size_t)(n0 + row) * K + k0 + c4];
            Bs[c4+0][row] = w.x; Bs[c4+1][row] = w.y; Bs[c4+2][row] = w.z; Bs[c4+3][row] = w.w;
        }
        __syncthreads();
        #pragma unroll
        for (int k = 0; k < 16; k++) {
            float ar[8], br[8];
            *(float4*)(ar)   = *(const float4*)&As[k][ty * 8];
            *(float4*)(ar+4) = *(const float4*)&As[k][ty * 8 + 4];
            *(float4*)(br)   = *(const float4*)&Bs[k][tx * 8];
            *(float4*)(br+4) = *(const float4*)&Bs[k][tx * 8 + 4];
            #pragma unroll
            for (int i = 0; i < 8; i++)
                #pragma unroll
                for (int jj = 0; jj < 8; jj++)
                    acc[i][jj] = fmaf(ar[i], br[jj], acc[i][jj]);
        }
        __syncthreads();
    }
    float bb[8];
    #pragma unroll
    for (int jj = 0; jj < 8; jj++) { int c = n0 + tx * 8 + jj; bb[jj] = b1[c] + b2[c]; }
    #pragma unroll
    for (int i = 0; i < 8; i++) {
        size_t row = (size_t)(m0 + ty * 8 + i);
        float4 o0 = {acc[i][0]+bb[0], acc[i][1]+bb[1], acc[i][2]+bb[2], acc[i][3]+bb[3]};
        float4 o1 = {acc[i][4]+bb[4], acc[i][5]+bb[5], acc[i][6]+bb[6], acc[i][7]+bb[7]};
        *(float4*)&C[row * N + n0 + tx * 8]     = o0;
        *(float4*)&C[row * N + n0 + tx * 8 + 4] = o1;
    }
}

// ============ Layer 2: H=64, CTA per chain ============
#define L2_SMEM_BYTES (32 * 256 * 8 + 64 * 4 + 256 * 4)
__global__ __launch_bounds__(256, 1) void lstm2_kernel(
    const float* __restrict__ xg, const float* __restrict__ Whh,
    float* __restrict__ y2)
{
    extern __shared__ char smraw[];
    ull*   sW2 = (ull*)smraw;
    float* sh  = (float*)(smraw + 32 * 256 * 8);
    float* sg  = sh + 64;
    const int r = threadIdx.x;
    const int b = blockIdx.x >> 1, dir = blockIdx.x & 1;
    const int gate = r >> 6, j = r & 63;
    const float* WhhD = Whh + (size_t)dir * 256 * 64;

    for (int i = r; i < 32 * 256; i += 256) {
        int kp = i >> 8, rr = i & 255;
        sW2[i] = *(const ull*)(WhhD + rr * 64 + 2 * kp);
    }
    if (r < 64) sh[r] = 0.0f;
    float cc = 0.0f;
    __syncthreads();

    const float* xgb = xg + (size_t)b * TT * 512 + dir * 256 + r;
    const int t0 = dir ? (TT - 1) : 0;
    float xt = __ldg(xgb + (size_t)t0 * 512);

    for (int s = 0; s < TT; s++) {
        const int t = dir ? (TT - 1 - s) : s;
        float xnext = 0.0f;
        if (s + 1 < TT) {
            const int tn = dir ? (TT - 2 - s) : (s + 1);
            xnext = __ldg(xgb + (size_t)tn * 512);
        }
        ull accA = 0ull, accB = 0ull;
        #pragma unroll
        for (int kp = 0; kp < 32; kp += 2) {
            fma2(accA, sW2[kp * 256 + r],       *(const ull*)(sh + 2 * kp));
            fma2(accB, sW2[(kp + 1) * 256 + r], *(const ull*)(sh + 2 * kp + 2));
        }
        float alo, ahi, blo, bhi;
        upk(accA, alo, ahi); upk(accB, blo, bhi);
        float v = xt + (alo + ahi) + (blo + bhi);
        sg[r] = (gate == 2) ? mytanh(v) : mysig(v);
        __syncthreads();
        if (r < 64) {
            float i_ = sg[j], f_ = sg[j+64], gg = sg[j+128], o_ = sg[j+192];
            cc = fmaf(f_, cc, i_ * gg);
            float h = o_ * mytanh(cc);
            sh[j] = h;
            y2[((size_t)b * TT + t) * 128 + dir * 64 + j] = h;
        }
        __syncthreads();
        xt = xnext;
    }
}

// ============ Layer 3 + mean: warp per chain ============
__global__ __launch_bounds__(256, 1) void lstm3_kernel(
    const float* __restrict__ xg, const float* __restrict__ Whh,
    float* __restrict__ s3)
{
    __shared__ float shh[8][16];
    const int tid = threadIdx.x, wid = tid >> 5, lane = tid & 31;
    const int pg = blockIdx.x * 8 + wid;
    const int b = pg >> 1, dir = pg & 1;
    const int r0 = lane, r1 = lane + 32;
    const float* WhhD = Whh + (size_t)dir * 64 * 16;
    float* shp = shh[wid];

    ull w0[8], w1[8];
    #pragma unroll
    for (int kp = 0; kp < 8; kp++) {
        w0[kp] = *(const ull*)(WhhD + r0 * 16 + 2 * kp);
        w1[kp] = *(const ull*)(WhhD + r1 * 16 + 2 * kp);
    }
    if (lane < 16) shp[lane] = 0.0f;
    float cc = 0.0f, sum = 0.0f;
    __syncwarp();

    const float* xgb = xg + (size_t)b * TT * 128 + dir * 64;
    const int t0 = dir ? (TT - 1) : 0;
    float xt0 = __ldg(xgb + (size_t)t0 * 128 + r0);
    float xt1 = __ldg(xgb + (size_t)t0 * 128 + r1);

    for (int s = 0; s < TT; s++) {
        float xn0 = 0.0f, xn1 = 0.0f;
        if (s + 1 < TT) {
            const int tn = dir ? (TT - 2 - s) : (s + 1);
            xn0 = __ldg(xgb + (size_t)tn * 128 + r0);
            xn1 = __ldg(xgb + (size_t)tn * 128 + r1);
        }
        ull a0 = 0ull, a1 = 0ull;
        #pragma unroll
        for (int kp = 0; kp < 8; kp++) {
            ull hb = *(const ull*)(shp + 2 * kp);
            fma2(a0, w0[kp], hb);
            fma2(a1, w1[kp], hb);
        }
        float l0, h0, l1, h1;
        upk(a0, l0, h0); upk(a1, l1, h1);
        float v0 = xt0 + l0 + h0, v1 = xt1 + l1 + h1;
        float g0 = mysig(v0);
        float g1 = (lane < 16) ? mytanh(v1) : mysig(v1);
        float f_ = __shfl_down_sync(0xffffffffu, g0, 16);
        float o_ = __shfl_down_sync(0xffffffffu, g1, 16);
        if (lane < 16) {
            cc = fmaf(f_, cc, g0 * g1);
            float h = o_ * mytanh(cc);
            shp[lane] = h;
            sum += h;
        }
        __syncwarp();
        xt0 = xn0; xt1 = xn1;
    }
    if (lane < 16) s3[b * 32 + dir * 16 + lane] = sum * (1.0f / TT);
}

// ============ MLP head ============
__global__ void mlp_kernel(
    const float* __restrict__ s3,
    const float* __restrict__ hW1, const float* __restrict__ hb1,
    const float* __restrict__ hW2, const float* __restrict__ hb2,
    const float* __restrict__ hW3, const float* __restrict__ hb3,
    float* __restrict__ out)
{
    int b = blockIdx.x * blockDim.x + threadIdx.x;
    if (b >= BB) return;
    float s[32];
    #pragma unroll
    for (int k = 0; k < 32; k++) s[k] = s3[b * 32 + k];
    float h1[64];
    for (int o = 0; o < 64; o++) {
        float a = hb1[o];
        #pragma unroll
        for (int k = 0; k < 32; k++) a = fmaf(s[k], hW1[o * 32 + k], a);
        h1[o] = fmaxf(a, 0.0f);
    }
    float h2[16];
    for (int o = 0; o < 16; o++) {
        float a = hb2[o];
        #pragma unroll
        for (int k = 0; k < 64; k++) a = fmaf(h1[k], hW2[o * 64 + k], a);
        h2[o] = fmaxf(a, 0.0f);
    }
    for (int o = 0; o < 20; o++) {
        float a = hb3[o];
        #pragma unroll
        for (int k = 0; k < 16; k++) a = fmaf(h2[k], hW3[o * 16 + k], a);
        out[b * 20 + o] = a;
    }
}

extern "C" void kernel_launch(void* const* d_in, const int* in_sizes, int n_in,
                              void* d_out, int out_size)
{
    const float* x    = (const float*)d_in[0];
    const float* Wih1 = (const float*)d_in[1];
    const float* Whh1 = (const float*)d_in[2];
    const float* bih1 = (const float*)d_in[3];
    const float* bhh1 = (const float*)d_in[4];
    const float* Wih2 = (const float*)d_in[5];
    const float* Whh2 = (const float*)d_in[6];
    const float* bih2 = (const float*)d_in[7];
    const float* bhh2 = (const float*)d_in[8];
    const float* Wih3 = (const float*)d_in[9];
    const float* Whh3 = (const float*)d_in[10];
    const float* bih3 = (const float*)d_in[11];
    const float* bhh3 = (const float*)d_in[12];
    const float* hW1  = (const float*)d_in[13];
    const float* hb1  = (const float*)d_in[14];
    const float* hW2  = (const float*)d_in[15];
    const float* hb2  = (const float*)d_in[16];
    const float* hW3  = (const float*)d_in[17];
    const float* hb3  = (const float*)d_in[18];
    float* out = (float*)d_out;

    __nv_bfloat16 *y1h, *y1l, *w2h, *w2l;
    float *xg2, *y2, *xg3, *s3;
    cudaGetSymbolAddress((void**)&y1h, g_y1h);
    cudaGetSymbolAddress((void**)&y1l, g_y1l);
    cudaGetSymbolAddress((void**)&w2h, g_w2h);
    cudaGetSymbolAddress((void**)&w2l, g_w2l);
    cudaGetSymbolAddress((void**)&xg2, g_xg2);
    cudaGetSymbolAddress((void**)&y2,  g_y2);
    cudaGetSymbolAddress((void**)&xg3, g_xg3);
    cudaGetSymbolAddress((void**)&s3,  g_sum3);

    static bool attr_set = false;
    if (!attr_set) {
        cudaFuncSetAttribute(lstm1_mma,
            cudaFuncAttributeMaxDynamicSharedMemorySize, L1_SMEM);
        cudaFuncSetAttribute(lstm2_kernel,
            cudaFuncAttributeMaxDynamicSharedMemorySize, L2_SMEM_BYTES);
        attr_set = true;
    }

    const int M = BB * TT;
    wsplit_kernel<<<512, 256>>>(Wih2, w2h, w2l, 512 * 256);
    lstm1_mma<<<dim3(64, 2), 512, L1_SMEM>>>(x, Wih1, Whh1, bih1, bhh1, y1h, y1l);
    gemm1_hmma<<<dim3(4, M / 128), 256>>>(y1h, y1l, w2h, w2l, bih2, bhh2, xg2);
    lstm2_kernel<<<512, 256, L2_SMEM_BYTES>>>(xg2, Whh2, y2);
    gemm_bias_kernel<<<dim3(1, M / 128), 256>>>(y2, Wih3, bih3, bhh3, xg3, 128, 128);
    lstm3_kernel<<<64, 256>>>(xg3, Whh3, s3);
    mlp_kernel<<<1, 256>>>(s3, hW1, hb1, hW2, hb2, hW3, hb3, out);
}